// round 1
// baseline (speedup 1.0000x reference)
#include <cuda_runtime.h>
#include <math.h>

#define BATCH 8192
#define PROTO 4096
#define DIM   1024
#define HEADS 16
#define DH    64
#define KSEL  6

// ---------------- device scratch (no allocation allowed) ----------------
__device__ float g_Wqc[DIM * DIM];
__device__ float g_Wkc[DIM * DIM];
__device__ float g_Wvc[DIM * DIM];
__device__ float g_bqc[DIM];
__device__ float g_bkc[DIM];
__device__ float g_bvc[DIM];
__device__ float g_qh[BATCH * DIM];
__device__ float g_Kb[PROTO * DIM];
__device__ float g_Vb[PROTO * DIM];
__device__ float g_ctx[BATCH * DIM];
__device__ int   g_topk[BATCH * KSEL];

// ---------------- GEMM: C[M,N] = A[M,K] @ B[K,N]  (row-major, no bias) ----
// For weight combines: Wc = W_attn(1024x1024) @ W_proj(1024x1024)
__global__ void gemm_ab_kernel(const float* __restrict__ A,
                               const float* __restrict__ B,
                               float* __restrict__ C,
                               int M, int N, int K) {
    __shared__ float As[16][65];
    __shared__ float Bs[16][65];
    const int tid = threadIdx.x;           // 256 threads
    const int tx = tid % 16, ty = tid / 16;
    const int m0 = blockIdx.y * 64, n0 = blockIdx.x * 64;

    float acc[4][4] = {};
    for (int k0 = 0; k0 < K; k0 += 16) {
        // A tile: 64 rows x 16 k
        #pragma unroll
        for (int idx = tid; idx < 64 * 16; idx += 256) {
            int r = idx >> 4, c = idx & 15;
            As[c][r] = A[(size_t)(m0 + r) * K + k0 + c];
        }
        // B tile: 16 k x 64 cols (coalesced)
        #pragma unroll
        for (int idx = tid; idx < 64 * 16; idx += 256) {
            int r = idx & 63, c = idx >> 6;
            Bs[c][r] = B[(size_t)(k0 + c) * N + n0 + r];
        }
        __syncthreads();
        #pragma unroll
        for (int kk = 0; kk < 16; kk++) {
            float a[4], b[4];
            #pragma unroll
            for (int i = 0; i < 4; i++) a[i] = As[kk][ty * 4 + i];
            #pragma unroll
            for (int j = 0; j < 4; j++) b[j] = Bs[kk][tx * 4 + j];
            #pragma unroll
            for (int i = 0; i < 4; i++)
                #pragma unroll
                for (int j = 0; j < 4; j++)
                    acc[i][j] = fmaf(a[i], b[j], acc[i][j]);
        }
        __syncthreads();
    }
    #pragma unroll
    for (int i = 0; i < 4; i++)
        #pragma unroll
        for (int j = 0; j < 4; j++)
            C[(size_t)(m0 + ty * 4 + i) * N + n0 + tx * 4 + j] = acc[i][j];
}

// ---------------- GEMM: C[M,N] = A[M,K] @ B[N,K]^T + bias[N] --------------
__global__ void gemm_abT_kernel(const float* __restrict__ A,
                                const float* __restrict__ B,
                                const float* __restrict__ bias,
                                float* __restrict__ C,
                                int M, int N, int K) {
    __shared__ float As[16][65];
    __shared__ float Bs[16][65];
    const int tid = threadIdx.x;           // 256 threads
    const int tx = tid % 16, ty = tid / 16;
    const int m0 = blockIdx.y * 64, n0 = blockIdx.x * 64;

    float acc[4][4] = {};
    for (int k0 = 0; k0 < K; k0 += 16) {
        #pragma unroll
        for (int idx = tid; idx < 64 * 16; idx += 256) {
            int r = idx >> 4, c = idx & 15;
            As[c][r] = A[(size_t)(m0 + r) * K + k0 + c];
        }
        #pragma unroll
        for (int idx = tid; idx < 64 * 16; idx += 256) {
            int r = idx >> 4, c = idx & 15;
            Bs[c][r] = B[(size_t)(n0 + r) * K + k0 + c];
        }
        __syncthreads();
        #pragma unroll
        for (int kk = 0; kk < 16; kk++) {
            float a[4], b[4];
            #pragma unroll
            for (int i = 0; i < 4; i++) a[i] = As[kk][ty * 4 + i];
            #pragma unroll
            for (int j = 0; j < 4; j++) b[j] = Bs[kk][tx * 4 + j];
            #pragma unroll
            for (int i = 0; i < 4; i++)
                #pragma unroll
                for (int j = 0; j < 4; j++)
                    acc[i][j] = fmaf(a[i], b[j], acc[i][j]);
        }
        __syncthreads();
    }
    #pragma unroll
    for (int i = 0; i < 4; i++)
        #pragma unroll
        for (int j = 0; j < 4; j++) {
            int n = n0 + tx * 4 + j;
            float bv = bias ? bias[n] : 0.0f;
            C[(size_t)(m0 + ty * 4 + i) * N + n] = acc[i][j] + bv;
        }
}

// ---------------- bias combine: b_out[i] = W[i,:]·b_in + b_add[i] ---------
__global__ void bias_combine_kernel(const float* __restrict__ W,
                                    const float* __restrict__ b_in,
                                    const float* __restrict__ b_add,
                                    float* __restrict__ b_out) {
    int i = blockIdx.x * blockDim.x + threadIdx.x;
    if (i >= DIM) return;
    float s = 0.0f;
    for (int t = 0; t < DIM; t++) s = fmaf(W[(size_t)i * DIM + t], b_in[t], s);
    b_out[i] = s + b_add[i];
}

// ---------------- top-6 per row (matches jax.lax.top_k ordering) ----------
__global__ void topk6_kernel(const float* __restrict__ logits,
                             int* __restrict__ topk) {
    const int b = blockIdx.x;
    const int tid = threadIdx.x;           // 256 threads
    __shared__ float row[PROTO];           // 16 KB
    __shared__ float rv[256];
    __shared__ int   ri[256];
    __shared__ int   sel[KSEL];

    const float* src = logits + (size_t)b * PROTO;
    for (int i = tid; i < PROTO; i += 256) row[i] = src[i];
    __syncthreads();

    for (int it = 0; it < KSEL; it++) {
        float bv = -INFINITY; int bi = PROTO;
        for (int i = tid; i < PROTO; i += 256) {
            bool taken = false;
            #pragma unroll
            for (int t = 0; t < KSEL; t++)
                if (t < it && sel[t] == i) taken = true;
            float v = row[i];
            if (!taken && (v > bv || (v == bv && i < bi))) { bv = v; bi = i; }
        }
        rv[tid] = bv; ri[tid] = bi;
        __syncthreads();
        for (int s = 128; s > 0; s >>= 1) {
            if (tid < s) {
                float v2 = rv[tid + s]; int i2 = ri[tid + s];
                if (v2 > rv[tid] || (v2 == rv[tid] && i2 < ri[tid])) {
                    rv[tid] = v2; ri[tid] = i2;
                }
            }
            __syncthreads();
        }
        if (tid == 0) { sel[it] = ri[0]; topk[(size_t)b * KSEL + it] = ri[0]; }
        __syncthreads();
    }
}

// ---------------- per-row attention over 6 selected prototypes ------------
__global__ void attention_kernel(const float* __restrict__ qh,
                                 const float* __restrict__ Kb,
                                 const float* __restrict__ Vb,
                                 const int* __restrict__ topk,
                                 float* __restrict__ ctx,
                                 float* __restrict__ attn_out) {
    const int b = blockIdx.x;
    const int tid = threadIdx.x;           // 128 threads
    __shared__ float q_s[DIM];
    __shared__ float k_s[KSEL][DIM];
    __shared__ int   idx_s[KSEL];
    __shared__ float s_s[HEADS][KSEL];

    if (tid < KSEL) idx_s[tid] = topk[(size_t)b * KSEL + tid];
    __syncthreads();

    {
        const float4* q4 = (const float4*)(qh + (size_t)b * DIM);
        float4* qs4 = (float4*)q_s;
        for (int i = tid; i < DIM / 4; i += 128) qs4[i] = q4[i];
        for (int i = tid; i < KSEL * (DIM / 4); i += 128) {
            int j = i / (DIM / 4), c = i % (DIM / 4);
            ((float4*)k_s[j])[c] =
                ((const float4*)(Kb + (size_t)idx_s[j] * DIM))[c];
        }
    }
    __syncthreads();

    // scores: 16 heads x 6 keys
    for (int p = tid; p < HEADS * KSEL; p += 128) {
        int h = p / KSEL, j = p % KSEL;
        float dot = 0.0f;
        #pragma unroll
        for (int d = 0; d < DH; d++)
            dot = fmaf(q_s[h * DH + d], k_s[j][h * DH + d], dot);
        s_s[h][j] = dot * 0.125f;   // 1/sqrt(64)
    }
    __syncthreads();

    // softmax per head
    if (tid < HEADS) {
        int h = tid;
        float m = s_s[h][0];
        #pragma unroll
        for (int j = 1; j < KSEL; j++) m = fmaxf(m, s_s[h][j]);
        float e[KSEL], sum = 0.0f;
        #pragma unroll
        for (int j = 0; j < KSEL; j++) { e[j] = expf(s_s[h][j] - m); sum += e[j]; }
        float inv = 1.0f / sum;
        #pragma unroll
        for (int j = 0; j < KSEL; j++) s_s[h][j] = e[j] * inv;
    }
    __syncthreads();

    // head-averaged attention weights
    if (tid < KSEL) {
        float m = 0.0f;
        #pragma unroll
        for (int h = 0; h < HEADS; h++) m += s_s[h][tid];
        attn_out[(size_t)b * KSEL + tid] = m * (1.0f / HEADS);
    }

    // ctx = sum_j w[h][j] * V[idx_j]
    for (int d = tid; d < DIM; d += 128) {
        int h = d / DH;
        float acc = 0.0f;
        #pragma unroll
        for (int j = 0; j < KSEL; j++)
            acc = fmaf(s_s[h][j], Vb[(size_t)idx_s[j] * DIM + d], acc);
        ctx[(size_t)b * DIM + d] = acc;
    }
}

// ---------------- host launcher -------------------------------------------
extern "C" void kernel_launch(void* const* d_in, const int* in_sizes, int n_in,
                              void* d_out, int out_size) {
    const float* query  = (const float*)d_in[0];
    const float* bank   = (const float*)d_in[1];
    const float* logits = (const float*)d_in[2];
    const float* Wq_proj = (const float*)d_in[3];
    const float* bq_proj = (const float*)d_in[4];
    const float* Wp_proj = (const float*)d_in[5];
    const float* bp_proj = (const float*)d_in[6];
    const float* Wq = (const float*)d_in[7];
    const float* bq = (const float*)d_in[8];
    const float* Wk = (const float*)d_in[9];
    const float* bk = (const float*)d_in[10];
    const float* Wv = (const float*)d_in[11];
    const float* bv = (const float*)d_in[12];
    const float* Wo = (const float*)d_in[13];
    const float* bo = (const float*)d_in[14];

    float* out = (float*)d_out;
    float* out_ctx  = out;                          // [8192,1024]
    float* out_attn = out + (size_t)BATCH * DIM;    // [8192,6]

    float *Wqc, *Wkc, *Wvc, *bqc, *bkc, *bvc, *qh, *Kb, *Vb, *ctx;
    int* topk;
    cudaGetSymbolAddress((void**)&Wqc, g_Wqc);
    cudaGetSymbolAddress((void**)&Wkc, g_Wkc);
    cudaGetSymbolAddress((void**)&Wvc, g_Wvc);
    cudaGetSymbolAddress((void**)&bqc, g_bqc);
    cudaGetSymbolAddress((void**)&bkc, g_bkc);
    cudaGetSymbolAddress((void**)&bvc, g_bvc);
    cudaGetSymbolAddress((void**)&qh,  g_qh);
    cudaGetSymbolAddress((void**)&Kb,  g_Kb);
    cudaGetSymbolAddress((void**)&Vb,  g_Vb);
    cudaGetSymbolAddress((void**)&ctx, g_ctx);
    cudaGetSymbolAddress((void**)&topk, g_topk);

    dim3 blk(256);
    dim3 grid_1k(DIM / 64, DIM / 64);      // 1024x1024 combines

    // 1) combined weights: Wqc = Wq @ Wq_proj, Wkc = Wk @ Wp_proj, Wvc = Wv @ Wp_proj
    gemm_ab_kernel<<<grid_1k, blk>>>(Wq, Wq_proj, Wqc, DIM, DIM, DIM);
    gemm_ab_kernel<<<grid_1k, blk>>>(Wk, Wp_proj, Wkc, DIM, DIM, DIM);
    gemm_ab_kernel<<<grid_1k, blk>>>(Wv, Wp_proj, Wvc, DIM, DIM, DIM);

    // 2) combined biases
    bias_combine_kernel<<<4, 256>>>(Wq, bq_proj, bq, bqc);
    bias_combine_kernel<<<4, 256>>>(Wk, bp_proj, bk, bkc);
    bias_combine_kernel<<<4, 256>>>(Wv, bp_proj, bv, bvc);

    // 3) qh = query @ Wqc^T + bqc            [8192,1024]
    gemm_abT_kernel<<<dim3(DIM / 64, BATCH / 64), blk>>>(query, Wqc, bqc, qh,
                                                         BATCH, DIM, DIM);
    // 4) K_bank / V_bank on the 4096 unique prototypes
    gemm_abT_kernel<<<dim3(DIM / 64, PROTO / 64), blk>>>(bank, Wkc, bkc, Kb,
                                                         PROTO, DIM, DIM);
    gemm_abT_kernel<<<dim3(DIM / 64, PROTO / 64), blk>>>(bank, Wvc, bvc, Vb,
                                                         PROTO, DIM, DIM);

    // 5) top-6 selection per row
    topk6_kernel<<<BATCH, 256>>>(logits, topk);

    // 6) attention (ctx + averaged weights)
    attention_kernel<<<BATCH, 128>>>(qh, Kb, Vb, topk, ctx, out_attn);

    // 7) out projection: context = ctx @ Wo^T + bo   -> d_out
    gemm_abT_kernel<<<dim3(DIM / 64, BATCH / 64), blk>>>(ctx, Wo, bo, out_ctx,
                                                         BATCH, DIM, DIM);
}

// round 2
// speedup vs baseline: 1.8868x; 1.8868x over previous
#include <cuda_runtime.h>
#include <math.h>

#define BATCH 8192
#define PROTO 4096
#define DIM   1024
#define HEADS 16
#define DH    64
#define KSEL  6

typedef unsigned long long ull;

// ---------------- device scratch ----------------
__device__ float g_Wqc[DIM * DIM];
__device__ float g_Wkc[DIM * DIM];
__device__ float g_Wvc[DIM * DIM];
__device__ float g_bqc[DIM];
__device__ float g_bkc[DIM];
__device__ float g_bvc[DIM];
__device__ float g_qh[BATCH * DIM];
__device__ float g_Kb[PROTO * DIM];
__device__ float g_Vb[PROTO * DIM];
__device__ float g_ctx[BATCH * DIM];
__device__ int   g_topk[BATCH * KSEL];

// ---------------- f32x2 packed helpers ----------------
__device__ __forceinline__ void fma2(ull& d, ull a, ull b) {
    asm("fma.rn.f32x2 %0, %1, %2, %0;" : "+l"(d) : "l"(a), "l"(b));
}
__device__ __forceinline__ ull pack2(float x, float y) {
    ull r; asm("mov.b64 %0, {%1, %2};" : "=l"(r) : "f"(x), "f"(y)); return r;
}
__device__ __forceinline__ float2 unpack2(ull v) {
    float2 r; asm("mov.b64 {%0, %1}, %2;" : "=f"(r.x), "=f"(r.y) : "l"(v)); return r;
}

// ---------------- batched GEMM (up to 3 problems via blockIdx.z) ----------
struct GemmBatch {
    const float* A[3];
    const float* B[3];
    const float* bias[3];
    float*       C[3];
};

// C[M,N] = A[M,K] @ op(B) + bias.  TRANSB: B is [N,K] (C = A B^T); else B is [K,N].
// Tiles: 128x128x16, 256 threads, 8x8 microtile, double-buffered smem,
// inner loop in packed fma.rn.f32x2.
template<bool TRANSB>
__global__ __launch_bounds__(256, 2)
void gemm_tile(GemmBatch p, int M, int N, int K) {
    __shared__ __align__(16) float As[2][16][128];
    __shared__ __align__(16) float Bs[2][16][128];

    const int z = blockIdx.z;
    const float* __restrict__ A    = p.A[z];
    const float* __restrict__ B    = p.B[z];
    const float* __restrict__ bias = p.bias[z];
    float* __restrict__ C          = p.C[z];

    const int tid = threadIdx.x;
    const int tx = tid & 15, ty = tid >> 4;
    const int m0 = blockIdx.y * 128, n0 = blockIdx.x * 128;

    // A tile load mapping (128 rows x 16 k): 2 float4 per thread
    const int t0 = tid, t1 = tid + 256;
    const int ar0 = t0 >> 2, ac0 = (t0 & 3) * 4;
    const int ar1 = t1 >> 2, ac1 = (t1 & 3) * 4;
    const float* Abase0 = A + (size_t)(m0 + ar0) * K + ac0;
    const float* Abase1 = A + (size_t)(m0 + ar1) * K + ac1;

    // B tile load mapping
    int br0, bc0, br1, bc1;
    const float *Bbase0, *Bbase1;
    if (TRANSB) {                       // B[N,K]: rows are n, cols are k
        br0 = ar0; bc0 = ac0; br1 = ar1; bc1 = ac1;
        Bbase0 = B + (size_t)(n0 + br0) * K + bc0;
        Bbase1 = B + (size_t)(n0 + br1) * K + bc1;
    } else {                            // B[K,N]: 16 rows x 128 cols
        br0 = t0 >> 5; bc0 = (t0 & 31) * 4;
        br1 = t1 >> 5; bc1 = (t1 & 31) * 4;
        Bbase0 = B + (size_t)br0 * N + n0 + bc0;
        Bbase1 = B + (size_t)br1 * N + n0 + bc1;
    }

    // prologue: tile 0 -> buf 0
    {
        float4 pa0 = *(const float4*)Abase0;
        float4 pa1 = *(const float4*)Abase1;
        float4 pb0 = *(const float4*)Bbase0;
        float4 pb1 = *(const float4*)Bbase1;
        As[0][ac0 + 0][ar0] = pa0.x; As[0][ac0 + 1][ar0] = pa0.y;
        As[0][ac0 + 2][ar0] = pa0.z; As[0][ac0 + 3][ar0] = pa0.w;
        As[0][ac1 + 0][ar1] = pa1.x; As[0][ac1 + 1][ar1] = pa1.y;
        As[0][ac1 + 2][ar1] = pa1.z; As[0][ac1 + 3][ar1] = pa1.w;
        if (TRANSB) {
            Bs[0][bc0 + 0][br0] = pb0.x; Bs[0][bc0 + 1][br0] = pb0.y;
            Bs[0][bc0 + 2][br0] = pb0.z; Bs[0][bc0 + 3][br0] = pb0.w;
            Bs[0][bc1 + 0][br1] = pb1.x; Bs[0][bc1 + 1][br1] = pb1.y;
            Bs[0][bc1 + 2][br1] = pb1.z; Bs[0][bc1 + 3][br1] = pb1.w;
        } else {
            *(float4*)&Bs[0][br0][bc0] = pb0;
            *(float4*)&Bs[0][br1][bc1] = pb1;
        }
    }
    __syncthreads();

    ull acc[8][4];
    #pragma unroll
    for (int i = 0; i < 8; i++)
        #pragma unroll
        for (int j = 0; j < 4; j++) acc[i][j] = 0ULL;

    const int nTiles = K / 16;
    for (int tIdx = 0; tIdx < nTiles; tIdx++) {
        const int buf = tIdx & 1;
        const bool has_next = (tIdx + 1) < nTiles;
        float4 pa0, pa1, pb0, pb1;
        if (has_next) {
            const int off = (tIdx + 1) * 16;
            pa0 = *(const float4*)(Abase0 + off);
            pa1 = *(const float4*)(Abase1 + off);
            if (TRANSB) {
                pb0 = *(const float4*)(Bbase0 + off);
                pb1 = *(const float4*)(Bbase1 + off);
            } else {
                pb0 = *(const float4*)(Bbase0 + (size_t)off * N);
                pb1 = *(const float4*)(Bbase1 + (size_t)off * N);
            }
        }

        #pragma unroll
        for (int kk = 0; kk < 16; kk++) {
            const float* as = &As[buf][kk][ty * 8];
            float4 a0 = *(const float4*)as;
            float4 a1 = *(const float4*)(as + 4);
            const ull* bp = (const ull*)&Bs[buf][kk][tx * 8];
            ull b0 = bp[0], b1 = bp[1], b2 = bp[2], b3 = bp[3];
            float av[8] = {a0.x, a0.y, a0.z, a0.w, a1.x, a1.y, a1.z, a1.w};
            #pragma unroll
            for (int i = 0; i < 8; i++) {
                ull a2 = pack2(av[i], av[i]);
                fma2(acc[i][0], a2, b0);
                fma2(acc[i][1], a2, b1);
                fma2(acc[i][2], a2, b2);
                fma2(acc[i][3], a2, b3);
            }
        }

        if (has_next) {
            const int nb = buf ^ 1;
            As[nb][ac0 + 0][ar0] = pa0.x; As[nb][ac0 + 1][ar0] = pa0.y;
            As[nb][ac0 + 2][ar0] = pa0.z; As[nb][ac0 + 3][ar0] = pa0.w;
            As[nb][ac1 + 0][ar1] = pa1.x; As[nb][ac1 + 1][ar1] = pa1.y;
            As[nb][ac1 + 2][ar1] = pa1.z; As[nb][ac1 + 3][ar1] = pa1.w;
            if (TRANSB) {
                Bs[nb][bc0 + 0][br0] = pb0.x; Bs[nb][bc0 + 1][br0] = pb0.y;
                Bs[nb][bc0 + 2][br0] = pb0.z; Bs[nb][bc0 + 3][br0] = pb0.w;
                Bs[nb][bc1 + 0][br1] = pb1.x; Bs[nb][bc1 + 1][br1] = pb1.y;
                Bs[nb][bc1 + 2][br1] = pb1.z; Bs[nb][bc1 + 3][br1] = pb1.w;
            } else {
                *(float4*)&Bs[nb][br0][bc0] = pb0;
                *(float4*)&Bs[nb][br1][bc1] = pb1;
            }
        }
        __syncthreads();
    }

    // epilogue
    float bb[8];
    #pragma unroll
    for (int u = 0; u < 8; u++)
        bb[u] = bias ? bias[n0 + tx * 8 + u] : 0.0f;
    #pragma unroll
    for (int i = 0; i < 8; i++) {
        float o[8];
        #pragma unroll
        for (int j = 0; j < 4; j++) {
            float2 v = unpack2(acc[i][j]);
            o[2 * j]     = v.x + bb[2 * j];
            o[2 * j + 1] = v.y + bb[2 * j + 1];
        }
        float* cp = C + (size_t)(m0 + ty * 8 + i) * N + n0 + tx * 8;
        *(float4*)cp       = make_float4(o[0], o[1], o[2], o[3]);
        *(float4*)(cp + 4) = make_float4(o[4], o[5], o[6], o[7]);
    }
}

// ---------------- batched bias combine: out[i] = W[i,:]·b_in + b_add[i] ----
struct BiasBatch {
    const float* W[3];
    const float* bin[3];
    const float* badd[3];
    float*       out[3];
};

__global__ void bias_combine_kernel(BiasBatch p) {
    const int z = blockIdx.y;
    const int warp = threadIdx.x >> 5, lane = threadIdx.x & 31;
    const int i = blockIdx.x * 8 + warp;
    const float* __restrict__ row = p.W[z] + (size_t)i * DIM;
    const float* __restrict__ bin = p.bin[z];
    float s = 0.0f;
    for (int t = lane; t < DIM; t += 32) s = fmaf(row[t], bin[t], s);
    #pragma unroll
    for (int o = 16; o; o >>= 1) s += __shfl_down_sync(0xffffffffu, s, o);
    if (lane == 0) p.out[z][i] = s + p.badd[z][i];
}

// ---------------- top-6 per row (single pass + merge) ----------------------
__global__ void topk6_kernel(const float* __restrict__ logits,
                             int* __restrict__ topk) {
    const int b = blockIdx.x;
    const int tid = threadIdx.x;   // 256
    const float* __restrict__ src = logits + (size_t)b * PROTO;

    float v[KSEL]; int ix[KSEL];
    #pragma unroll
    for (int q = 0; q < KSEL; q++) { v[q] = -INFINITY; ix[q] = 0x7fffffff; }

    #pragma unroll
    for (int pp = 0; pp < PROTO / 256; pp++) {
        int i = tid + pp * 256;
        float x = src[i];
        if (x > v[KSEL - 1]) {
            v[KSEL - 1] = x; ix[KSEL - 1] = i;
            #pragma unroll
            for (int q = KSEL - 1; q > 0; q--) {
                if (v[q] > v[q - 1]) {
                    float tv = v[q]; v[q] = v[q - 1]; v[q - 1] = tv;
                    int ti = ix[q]; ix[q] = ix[q - 1]; ix[q - 1] = ti;
                }
            }
        }
    }

    __shared__ float sv[256];
    __shared__ int   si[256];
    __shared__ int   swin;
    int head = 0;
    for (int t = 0; t < KSEL; t++) {
        sv[tid] = (head < KSEL) ? v[head] : -INFINITY;
        si[tid] = (head < KSEL) ? ix[head] : 0x7fffffff;
        __syncthreads();
        #pragma unroll
        for (int s = 128; s > 0; s >>= 1) {
            if (tid < s) {
                float ov = sv[tid + s]; int oi = si[tid + s];
                if (ov > sv[tid] || (ov == sv[tid] && oi < si[tid])) {
                    sv[tid] = ov; si[tid] = oi;
                }
            }
            __syncthreads();
        }
        if (tid == 0) { swin = si[0]; topk[(size_t)b * KSEL + t] = si[0]; }
        __syncthreads();
        if (head < KSEL && ix[head] == swin) head++;
    }
}

// ---------------- per-row attention over 6 selected prototypes ------------
__global__ void attention_kernel(const float* __restrict__ qh,
                                 const float* __restrict__ Kb,
                                 const float* __restrict__ Vb,
                                 const int* __restrict__ topk,
                                 float* __restrict__ ctx,
                                 float* __restrict__ attn_out) {
    const int b = blockIdx.x;
    const int tid = threadIdx.x;   // 128
    __shared__ float q_s[DIM];
    __shared__ float k_s[KSEL][DIM];
    __shared__ int   idx_s[KSEL];
    __shared__ float s_s[HEADS][KSEL];

    if (tid < KSEL) idx_s[tid] = topk[(size_t)b * KSEL + tid];
    __syncthreads();

    {
        const float4* q4 = (const float4*)(qh + (size_t)b * DIM);
        float4* qs4 = (float4*)q_s;
        for (int i = tid; i < DIM / 4; i += 128) qs4[i] = q4[i];
        for (int i = tid; i < KSEL * (DIM / 4); i += 128) {
            int j = i / (DIM / 4), c = i % (DIM / 4);
            ((float4*)k_s[j])[c] =
                ((const float4*)(Kb + (size_t)idx_s[j] * DIM))[c];
        }
    }
    __syncthreads();

    for (int p = tid; p < HEADS * KSEL; p += 128) {
        int h = p / KSEL, j = p % KSEL;
        float dot = 0.0f;
        #pragma unroll
        for (int d = 0; d < DH; d++)
            dot = fmaf(q_s[h * DH + d], k_s[j][h * DH + d], dot);
        s_s[h][j] = dot * 0.125f;
    }
    __syncthreads();

    if (tid < HEADS) {
        int h = tid;
        float m = s_s[h][0];
        #pragma unroll
        for (int j = 1; j < KSEL; j++) m = fmaxf(m, s_s[h][j]);
        float e[KSEL], sum = 0.0f;
        #pragma unroll
        for (int j = 0; j < KSEL; j++) { e[j] = expf(s_s[h][j] - m); sum += e[j]; }
        float inv = 1.0f / sum;
        #pragma unroll
        for (int j = 0; j < KSEL; j++) s_s[h][j] = e[j] * inv;
    }
    __syncthreads();

    if (tid < KSEL) {
        float m = 0.0f;
        #pragma unroll
        for (int h = 0; h < HEADS; h++) m += s_s[h][tid];
        attn_out[(size_t)b * KSEL + tid] = m * (1.0f / HEADS);
    }

    for (int d = tid; d < DIM; d += 128) {
        int h = d / DH;
        float acc = 0.0f;
        #pragma unroll
        for (int j = 0; j < KSEL; j++)
            acc = fmaf(s_s[h][j], Vb[(size_t)idx_s[j] * DIM + d], acc);
        ctx[(size_t)b * DIM + d] = acc;
    }
}

// ---------------- host launcher -------------------------------------------
extern "C" void kernel_launch(void* const* d_in, const int* in_sizes, int n_in,
                              void* d_out, int out_size) {
    const float* query  = (const float*)d_in[0];
    const float* bank   = (const float*)d_in[1];
    const float* logits = (const float*)d_in[2];
    const float* Wq_proj = (const float*)d_in[3];
    const float* bq_proj = (const float*)d_in[4];
    const float* Wp_proj = (const float*)d_in[5];
    const float* bp_proj = (const float*)d_in[6];
    const float* Wq = (const float*)d_in[7];
    const float* bq = (const float*)d_in[8];
    const float* Wk = (const float*)d_in[9];
    const float* bk = (const float*)d_in[10];
    const float* Wv = (const float*)d_in[11];
    const float* bv = (const float*)d_in[12];
    const float* Wo = (const float*)d_in[13];
    const float* bo = (const float*)d_in[14];

    float* out = (float*)d_out;
    float* out_ctx  = out;
    float* out_attn = out + (size_t)BATCH * DIM;

    float *Wqc, *Wkc, *Wvc, *bqc, *bkc, *bvc, *qh, *Kb, *Vb, *ctx;
    int* topk;
    cudaGetSymbolAddress((void**)&Wqc, g_Wqc);
    cudaGetSymbolAddress((void**)&Wkc, g_Wkc);
    cudaGetSymbolAddress((void**)&Wvc, g_Wvc);
    cudaGetSymbolAddress((void**)&bqc, g_bqc);
    cudaGetSymbolAddress((void**)&bkc, g_bkc);
    cudaGetSymbolAddress((void**)&bvc, g_bvc);
    cudaGetSymbolAddress((void**)&qh,  g_qh);
    cudaGetSymbolAddress((void**)&Kb,  g_Kb);
    cudaGetSymbolAddress((void**)&Vb,  g_Vb);
    cudaGetSymbolAddress((void**)&ctx, g_ctx);
    cudaGetSymbolAddress((void**)&topk, g_topk);

    // top-k is independent of everything else — launch first
    topk6_kernel<<<BATCH, 256>>>(logits, topk);

    // 1) fused weight combines: Wqc = Wq@Wq_proj, Wkc = Wk@Wp_proj, Wvc = Wv@Wp_proj
    {
        GemmBatch gb = {};
        gb.A[0] = Wq; gb.A[1] = Wk; gb.A[2] = Wv;
        gb.B[0] = Wq_proj; gb.B[1] = Wp_proj; gb.B[2] = Wp_proj;
        gb.C[0] = Wqc; gb.C[1] = Wkc; gb.C[2] = Wvc;
        gemm_tile<false><<<dim3(DIM / 128, DIM / 128, 3), 256>>>(gb, DIM, DIM, DIM);
    }

    // 2) fused bias combines
    {
        BiasBatch bb = {};
        bb.W[0] = Wq; bb.W[1] = Wk; bb.W[2] = Wv;
        bb.bin[0] = bq_proj; bb.bin[1] = bp_proj; bb.bin[2] = bp_proj;
        bb.badd[0] = bq; bb.badd[1] = bk; bb.badd[2] = bv;
        bb.out[0] = bqc; bb.out[1] = bkc; bb.out[2] = bvc;
        bias_combine_kernel<<<dim3(DIM / 8, 3), 256>>>(bb);
    }

    // 3) qh = query @ Wqc^T + bqc
    {
        GemmBatch gb = {};
        gb.A[0] = query; gb.B[0] = Wqc; gb.bias[0] = bqc; gb.C[0] = qh;
        gemm_tile<true><<<dim3(DIM / 128, BATCH / 128, 1), 256>>>(gb, BATCH, DIM, DIM);
    }

    // 4) K_bank / V_bank fused
    {
        GemmBatch gb = {};
        gb.A[0] = bank; gb.A[1] = bank;
        gb.B[0] = Wkc;  gb.B[1] = Wvc;
        gb.bias[0] = bkc; gb.bias[1] = bvc;
        gb.C[0] = Kb;   gb.C[1] = Vb;
        gemm_tile<true><<<dim3(DIM / 128, PROTO / 128, 2), 256>>>(gb, PROTO, DIM, DIM);
    }

    // 5) attention
    attention_kernel<<<BATCH, 128>>>(qh, Kb, Vb, topk, ctx, out_attn);

    // 6) out projection
    {
        GemmBatch gb = {};
        gb.A[0] = ctx; gb.B[0] = Wo; gb.bias[0] = bo; gb.C[0] = out_ctx;
        gemm_tile<true><<<dim3(DIM / 128, BATCH / 128, 1), 256>>>(gb, BATCH, DIM, DIM);
    }
}

// round 4
// speedup vs baseline: 2.8445x; 1.5076x over previous
#include <cuda_runtime.h>
#include <cuda_bf16.h>
#include <math.h>

#define BATCH 8192
#define PROTO 4096
#define DIM   1024
#define HEADS 16
#define DH    64
#define KSEL  6

typedef unsigned long long ull;
typedef unsigned int u32;

// ---------------- device scratch ----------------
__device__ float g_Wqc[DIM * DIM];
__device__ float g_Wkc[DIM * DIM];
__device__ float g_Wvc[DIM * DIM];
__device__ float g_bqc[DIM];
__device__ float g_bkc[DIM];
__device__ float g_bvc[DIM];
__device__ float g_qh[BATCH * DIM];
__device__ float g_Kb[PROTO * DIM];
__device__ float g_Vb[PROTO * DIM];
__device__ float g_ctx[BATCH * DIM];
__device__ int   g_topk[BATCH * KSEL];

// bf16 hi/lo splits, plain row-major [R][DIM]
__device__ __align__(16) __nv_bfloat16 g_q_hi[BATCH * DIM];
__device__ __align__(16) __nv_bfloat16 g_q_lo[BATCH * DIM];
__device__ __align__(16) __nv_bfloat16 g_bank_hi[PROTO * DIM];
__device__ __align__(16) __nv_bfloat16 g_bank_lo[PROTO * DIM];
__device__ __align__(16) __nv_bfloat16 g_Wqc_hi[DIM * DIM];
__device__ __align__(16) __nv_bfloat16 g_Wqc_lo[DIM * DIM];
__device__ __align__(16) __nv_bfloat16 g_Wkc_hi[DIM * DIM];
__device__ __align__(16) __nv_bfloat16 g_Wkc_lo[DIM * DIM];
__device__ __align__(16) __nv_bfloat16 g_Wvc_hi[DIM * DIM];
__device__ __align__(16) __nv_bfloat16 g_Wvc_lo[DIM * DIM];
__device__ __align__(16) __nv_bfloat16 g_Wo_hi[DIM * DIM];
__device__ __align__(16) __nv_bfloat16 g_Wo_lo[DIM * DIM];
__device__ __align__(16) __nv_bfloat16 g_ctx_hi[BATCH * DIM];
__device__ __align__(16) __nv_bfloat16 g_ctx_lo[BATCH * DIM];

// ---------------- low-level helpers ----------------
__device__ __forceinline__ u32 smem_u32(const void* p) {
    u32 a;
    asm("{ .reg .u64 t; cvta.to.shared.u64 t, %1; cvt.u32.u64 %0, t; }"
        : "=r"(a) : "l"(p));
    return a;
}
__device__ __forceinline__ void cp_async16(u32 dst, const void* src) {
    asm volatile("cp.async.cg.shared.global [%0], [%1], 16;"
                 :: "r"(dst), "l"(src) : "memory");
}
__device__ __forceinline__ void cp_commit() {
    asm volatile("cp.async.commit_group;" ::: "memory");
}
__device__ __forceinline__ void cp_wait1() {
    asm volatile("cp.async.wait_group 1;" ::: "memory");
}
__device__ __forceinline__ void cp_wait0() {
    asm volatile("cp.async.wait_group 0;" ::: "memory");
}
__device__ __forceinline__ void ldsm4(u32* d, u32 addr) {
    asm volatile("ldmatrix.sync.aligned.m8n8.x4.shared.b16 {%0,%1,%2,%3}, [%4];"
                 : "=r"(d[0]), "=r"(d[1]), "=r"(d[2]), "=r"(d[3]) : "r"(addr));
}
__device__ __forceinline__ void mma_bf16(float* c, const u32* a, u32 b0, u32 b1) {
    asm volatile("mma.sync.aligned.m16n8k16.row.col.f32.bf16.bf16.f32 "
                 "{%0,%1,%2,%3},{%4,%5,%6,%7},{%8,%9},{%0,%1,%2,%3};"
                 : "+f"(c[0]), "+f"(c[1]), "+f"(c[2]), "+f"(c[3])
                 : "r"(a[0]), "r"(a[1]), "r"(a[2]), "r"(a[3]), "r"(b0), "r"(b1));
}

// ---------------- split fp32 -> bf16 hi/lo (row-major) ----------------
__global__ void split_kernel(const float* __restrict__ X,
                             __nv_bfloat16* __restrict__ hi,
                             __nv_bfloat16* __restrict__ lo) {
    size_t id = ((size_t)blockIdx.x * 256 + threadIdx.x) * 8;
    const float4* src = (const float4*)(X + id);
    float4 a = src[0], b = src[1];
    float xs[8] = {a.x, a.y, a.z, a.w, b.x, b.y, b.z, b.w};
    __nv_bfloat16 h[8], l[8];
    #pragma unroll
    for (int i = 0; i < 8; i++) {
        h[i] = __float2bfloat16(xs[i]);
        l[i] = __float2bfloat16(xs[i] - __bfloat162float(h[i]));
    }
    *(uint4*)(hi + id) = *(uint4*)h;
    *(uint4*)(lo + id) = *(uint4*)l;
}

// ---------------- mma.sync GEMM: C[M,1024] = A[M,K]@B[1024,K]^T + bias ----
// bf16x3: C = Ahi Bhi^T + Ahi Blo^T + Alo Bhi^T, fp32 accum.
// Tile 128x128x32, 8 warps (4m x 2n), warp tile 32x64.
#define BK 32
#define SKB 40                        /* bf16 row stride in smem (80 B) */
#define TILE_SM (128 * SKB * 2)       /* 10240 B */
#define STAGE_SM (4 * TILE_SM)        /* Ahi, Alo, Bhi, Blo = 40960 B */
#define MMA_SMEM (2 * STAGE_SM)       /* 81920 B */

struct MmaB {
    const __nv_bfloat16 *Ahi[2], *Alo[2], *Bhi[2], *Blo[2];
    const float* bias[2];
    float* C[2];
};

__global__ __launch_bounds__(256, 1)
void mma_gemm(MmaB p, int M) {
    extern __shared__ __align__(16) char sm[];
    const u32 sbase = smem_u32(sm);

    const int z = blockIdx.z;
    const __nv_bfloat16* __restrict__ Ahi = p.Ahi[z];
    const __nv_bfloat16* __restrict__ Alo = p.Alo[z];
    const __nv_bfloat16* __restrict__ Bhi = p.Bhi[z];
    const __nv_bfloat16* __restrict__ Blo = p.Blo[z];
    const float* __restrict__ bias = p.bias[z];
    float* __restrict__ C = p.C[z];

    const int tid = threadIdx.x, lane = tid & 31, wid = tid >> 5;
    const int wm = wid >> 1, wn = wid & 1;
    const int m0 = blockIdx.y * 128, n0 = blockIdx.x * 128;

    // per-thread load coords: 2 chunks of 16B per tile per stage
    const int ch0 = tid, ch1 = tid + 256;
    const int lr0 = ch0 >> 2, ls0 = ch0 & 3;
    const int lr1 = ch1 >> 2, ls1 = ch1 & 3;
    const __nv_bfloat16* gA0hi = Ahi + (size_t)(m0 + lr0) * DIM + ls0 * 8;
    const __nv_bfloat16* gA1hi = Ahi + (size_t)(m0 + lr1) * DIM + ls1 * 8;
    const __nv_bfloat16* gA0lo = Alo + (size_t)(m0 + lr0) * DIM + ls0 * 8;
    const __nv_bfloat16* gA1lo = Alo + (size_t)(m0 + lr1) * DIM + ls1 * 8;
    const __nv_bfloat16* gB0hi = Bhi + (size_t)(n0 + lr0) * DIM + ls0 * 8;
    const __nv_bfloat16* gB1hi = Bhi + (size_t)(n0 + lr1) * DIM + ls1 * 8;
    const __nv_bfloat16* gB0lo = Blo + (size_t)(n0 + lr0) * DIM + ls0 * 8;
    const __nv_bfloat16* gB1lo = Blo + (size_t)(n0 + lr1) * DIM + ls1 * 8;
    const u32 d0 = lr0 * (SKB * 2) + ls0 * 16;
    const u32 d1 = lr1 * (SKB * 2) + ls1 * 16;

    #define LOAD_STAGE(s)                                                 \
    do {                                                                  \
        const u32 st_ = sbase + ((s) & 1) * STAGE_SM;                     \
        const int k0_ = (s) * BK;                                         \
        cp_async16(st_ + d0,               gA0hi + k0_);                  \
        cp_async16(st_ + d1,               gA1hi + k0_);                  \
        cp_async16(st_ + TILE_SM + d0,     gA0lo + k0_);                  \
        cp_async16(st_ + TILE_SM + d1,     gA1lo + k0_);                  \
        cp_async16(st_ + 2 * TILE_SM + d0, gB0hi + k0_);                  \
        cp_async16(st_ + 2 * TILE_SM + d1, gB1hi + k0_);                  \
        cp_async16(st_ + 3 * TILE_SM + d0, gB0lo + k0_);                  \
        cp_async16(st_ + 3 * TILE_SM + d1, gB1lo + k0_);                  \
        cp_commit();                                                      \
    } while (0)

    float c[2][8][4];
    #pragma unroll
    for (int i = 0; i < 2; i++)
        #pragma unroll
        for (int j = 0; j < 8; j++)
            #pragma unroll
            for (int q = 0; q < 4; q++) c[i][j][q] = 0.0f;

    const int NS = DIM / BK;   // 32 stages
    LOAD_STAGE(0);

    const u32 rowoff = (lane & 15) * (SKB * 2) + (lane >> 4) * 16;

    #pragma unroll 2
    for (int s = 0; s < NS; s++) {
        if (s + 1 < NS) { LOAD_STAGE(s + 1); cp_wait1(); }
        else           { cp_wait0(); }
        __syncthreads();

        const u32 st = sbase + (s & 1) * STAGE_SM;
        const u32 aHiB = st + (wm * 32) * (SKB * 2);
        const u32 aLoB = st + TILE_SM + (wm * 32) * (SKB * 2);
        const u32 bHiB = st + 2 * TILE_SM + (wn * 64) * (SKB * 2);
        const u32 bLoB = st + 3 * TILE_SM + (wn * 64) * (SKB * 2);

        #pragma unroll
        for (int kk = 0; kk < 2; kk++) {
            const u32 ko = kk * 32;   // 16 bf16 = 32 B
            u32 ah[2][4], al[2][4];
            ldsm4(ah[0], aHiB + rowoff + ko);
            ldsm4(ah[1], aHiB + 16 * (SKB * 2) + rowoff + ko);
            ldsm4(al[0], aLoB + rowoff + ko);
            ldsm4(al[1], aLoB + 16 * (SKB * 2) + rowoff + ko);
            u32 bh[4][4], bl[4][4];
            #pragma unroll
            for (int g = 0; g < 4; g++) {
                ldsm4(bh[g], bHiB + g * 16 * (SKB * 2) + rowoff + ko);
                ldsm4(bl[g], bLoB + g * 16 * (SKB * 2) + rowoff + ko);
            }
            #pragma unroll
            for (int mi = 0; mi < 2; mi++)
                #pragma unroll
                for (int g = 0; g < 4; g++)
                    #pragma unroll
                    for (int sub = 0; sub < 2; sub++) {
                        float* cc = c[mi][g * 2 + sub];
                        mma_bf16(cc, ah[mi], bh[g][sub], bh[g][sub + 2]);
                        mma_bf16(cc, ah[mi], bl[g][sub], bl[g][sub + 2]);
                        mma_bf16(cc, al[mi], bh[g][sub], bh[g][sub + 2]);
                    }
        }
        __syncthreads();
    }

    // epilogue: C frag layout m16n8: c0,c1 -> row lane/4, cols 2(lane&3)+{0,1};
    // c2,c3 -> row+8
    #pragma unroll
    for (int mi = 0; mi < 2; mi++) {
        const int row = m0 + wm * 32 + mi * 16 + (lane >> 2);
        #pragma unroll
        for (int ni = 0; ni < 8; ni++) {
            const int col = n0 + wn * 64 + ni * 8 + 2 * (lane & 3);
            float2 bv = *(const float2*)(bias + col);
            const float* cc = c[mi][ni];
            *(float2*)&C[(size_t)row * DIM + col] =
                make_float2(cc[0] + bv.x, cc[1] + bv.y);
            *(float2*)&C[(size_t)(row + 8) * DIM + col] =
                make_float2(cc[2] + bv.x, cc[3] + bv.y);
        }
    }
    #undef LOAD_STAGE
}

// ---------------- FFMA2 GEMM for the 3 weight combines (A@B) --------------
__device__ __forceinline__ void fma2(ull& d, ull a, ull b) {
    asm("fma.rn.f32x2 %0, %1, %2, %0;" : "+l"(d) : "l"(a), "l"(b));
}
__device__ __forceinline__ ull pack2(float x, float y) {
    ull r; asm("mov.b64 %0, {%1, %2};" : "=l"(r) : "f"(x), "f"(y)); return r;
}
__device__ __forceinline__ float2 unpack2(ull v) {
    float2 r; asm("mov.b64 {%0, %1}, %2;" : "=f"(r.x), "=f"(r.y) : "l"(v)); return r;
}

struct GemmBatch {
    const float* A[3];
    const float* B[3];
    float*       C[3];
};

__global__ __launch_bounds__(256, 2)
void gemm_combine(GemmBatch p, int M, int N, int K) {
    __shared__ __align__(16) float As[2][16][128];
    __shared__ __align__(16) float Bs[2][16][128];

    const int z = blockIdx.z;
    const float* __restrict__ A = p.A[z];
    const float* __restrict__ B = p.B[z];
    float* __restrict__ C       = p.C[z];

    const int tid = threadIdx.x;
    const int tx = tid & 15, ty = tid >> 4;
    const int m0 = blockIdx.y * 128, n0 = blockIdx.x * 128;

    const int t0 = tid, t1 = tid + 256;
    const int ar0 = t0 >> 2, ac0 = (t0 & 3) * 4;
    const int ar1 = t1 >> 2, ac1 = (t1 & 3) * 4;
    const float* Abase0 = A + (size_t)(m0 + ar0) * K + ac0;
    const float* Abase1 = A + (size_t)(m0 + ar1) * K + ac1;
    const int br0 = t0 >> 5, bc0 = (t0 & 31) * 4;
    const int br1 = t1 >> 5, bc1 = (t1 & 31) * 4;
    const float* Bbase0 = B + (size_t)br0 * N + n0 + bc0;
    const float* Bbase1 = B + (size_t)br1 * N + n0 + bc1;

    {
        float4 pa0 = *(const float4*)Abase0;
        float4 pa1 = *(const float4*)Abase1;
        As[0][ac0 + 0][ar0] = pa0.x; As[0][ac0 + 1][ar0] = pa0.y;
        As[0][ac0 + 2][ar0] = pa0.z; As[0][ac0 + 3][ar0] = pa0.w;
        As[0][ac1 + 0][ar1] = pa1.x; As[0][ac1 + 1][ar1] = pa1.y;
        As[0][ac1 + 2][ar1] = pa1.z; As[0][ac1 + 3][ar1] = pa1.w;
        *(float4*)&Bs[0][br0][bc0] = *(const float4*)Bbase0;
        *(float4*)&Bs[0][br1][bc1] = *(const float4*)Bbase1;
    }
    __syncthreads();

    ull acc[8][4];
    #pragma unroll
    for (int i = 0; i < 8; i++)
        #pragma unroll
        for (int j = 0; j < 4; j++) acc[i][j] = 0ULL;

    const int nTiles = K / 16;
    for (int tIdx = 0; tIdx < nTiles; tIdx++) {
        const int buf = tIdx & 1;
        const bool has_next = (tIdx + 1) < nTiles;
        float4 pa0, pa1, pb0, pb1;
        if (has_next) {
            const int off = (tIdx + 1) * 16;
            pa0 = *(const float4*)(Abase0 + off);
            pa1 = *(const float4*)(Abase1 + off);
            pb0 = *(const float4*)(Bbase0 + (size_t)off * N);
            pb1 = *(const float4*)(Bbase1 + (size_t)off * N);
        }
        #pragma unroll
        for (int kk = 0; kk < 16; kk++) {
            const float* as = &As[buf][kk][ty * 8];
            float4 a0 = *(const float4*)as;
            float4 a1 = *(const float4*)(as + 4);
            const ull* bp = (const ull*)&Bs[buf][kk][tx * 8];
            ull b0 = bp[0], b1 = bp[1], b2 = bp[2], b3 = bp[3];
            float av[8] = {a0.x, a0.y, a0.z, a0.w, a1.x, a1.y, a1.z, a1.w};
            #pragma unroll
            for (int i = 0; i < 8; i++) {
                ull a2 = pack2(av[i], av[i]);
                fma2(acc[i][0], a2, b0);
                fma2(acc[i][1], a2, b1);
                fma2(acc[i][2], a2, b2);
                fma2(acc[i][3], a2, b3);
            }
        }
        if (has_next) {
            const int nb = buf ^ 1;
            As[nb][ac0 + 0][ar0] = pa0.x; As[nb][ac0 + 1][ar0] = pa0.y;
            As[nb][ac0 + 2][ar0] = pa0.z; As[nb][ac0 + 3][ar0] = pa0.w;
            As[nb][ac1 + 0][ar1] = pa1.x; As[nb][ac1 + 1][ar1] = pa1.y;
            As[nb][ac1 + 2][ar1] = pa1.z; As[nb][ac1 + 3][ar1] = pa1.w;
            *(float4*)&Bs[nb][br0][bc0] = pb0;
            *(float4*)&Bs[nb][br1][bc1] = pb1;
        }
        __syncthreads();
    }

    #pragma unroll
    for (int i = 0; i < 8; i++) {
        float o[8];
        #pragma unroll
        for (int j = 0; j < 4; j++) {
            float2 v = unpack2(acc[i][j]);
            o[2 * j] = v.x; o[2 * j + 1] = v.y;
        }
        float* cp = C + (size_t)(m0 + ty * 8 + i) * N + n0 + tx * 8;
        *(float4*)cp       = make_float4(o[0], o[1], o[2], o[3]);
        *(float4*)(cp + 4) = make_float4(o[4], o[5], o[6], o[7]);
    }
}

// ---------------- batched bias combine ----------------
struct BiasBatch {
    const float* W[3];
    const float* bin[3];
    const float* badd[3];
    float*       out[3];
};

__global__ void bias_combine_kernel(BiasBatch p) {
    const int z = blockIdx.y;
    const int warp = threadIdx.x >> 5, lane = threadIdx.x & 31;
    const int i = blockIdx.x * 8 + warp;
    const float* __restrict__ row = p.W[z] + (size_t)i * DIM;
    const float* __restrict__ bin = p.bin[z];
    float s = 0.0f;
    for (int t = lane; t < DIM; t += 32) s = fmaf(row[t], bin[t], s);
    #pragma unroll
    for (int o = 16; o; o >>= 1) s += __shfl_down_sync(0xffffffffu, s, o);
    if (lane == 0) p.out[z][i] = s + p.badd[z][i];
}

// ---------------- top-6 per row ----------------
__global__ void topk6_kernel(const float* __restrict__ logits,
                             int* __restrict__ topk) {
    const int b = blockIdx.x;
    const int tid = threadIdx.x;   // 256
    const float* __restrict__ src = logits + (size_t)b * PROTO;

    float v[KSEL]; int ix[KSEL];
    #pragma unroll
    for (int q = 0; q < KSEL; q++) { v[q] = -INFINITY; ix[q] = 0x7fffffff; }

    #pragma unroll
    for (int pp = 0; pp < PROTO / 256; pp++) {
        int i = tid + pp * 256;
        float x = src[i];
        if (x > v[KSEL - 1]) {
            v[KSEL - 1] = x; ix[KSEL - 1] = i;
            #pragma unroll
            for (int q = KSEL - 1; q > 0; q--) {
                if (v[q] > v[q - 1]) {
                    float tv = v[q]; v[q] = v[q - 1]; v[q - 1] = tv;
                    int ti = ix[q]; ix[q] = ix[q - 1]; ix[q - 1] = ti;
                }
            }
        }
    }

    __shared__ float sv[256];
    __shared__ int   si[256];
    __shared__ int   swin;
    int head = 0;
    for (int t = 0; t < KSEL; t++) {
        sv[tid] = (head < KSEL) ? v[head] : -INFINITY;
        si[tid] = (head < KSEL) ? ix[head] : 0x7fffffff;
        __syncthreads();
        #pragma unroll
        for (int s = 128; s > 0; s >>= 1) {
            if (tid < s) {
                float ov = sv[tid + s]; int oi = si[tid + s];
                if (ov > sv[tid] || (ov == sv[tid] && oi < si[tid])) {
                    sv[tid] = ov; si[tid] = oi;
                }
            }
            __syncthreads();
        }
        if (tid == 0) { swin = si[0]; topk[(size_t)b * KSEL + t] = si[0]; }
        __syncthreads();
        if (head < KSEL && ix[head] == swin) head++;
    }
}

// ---------------- per-row attention ----------------
__global__ void attention_kernel(const float* __restrict__ qh,
                                 const float* __restrict__ Kb,
                                 const float* __restrict__ Vb,
                                 const int* __restrict__ topk,
                                 float* __restrict__ ctx,
                                 float* __restrict__ attn_out) {
    const int b = blockIdx.x;
    const int tid = threadIdx.x;   // 128
    __shared__ float q_s[DIM];
    __shared__ float k_s[KSEL][DIM];
    __shared__ int   idx_s[KSEL];
    __shared__ float s_s[HEADS][KSEL];

    if (tid < KSEL) idx_s[tid] = topk[(size_t)b * KSEL + tid];
    __syncthreads();

    {
        const float4* q4 = (const float4*)(qh + (size_t)b * DIM);
        float4* qs4 = (float4*)q_s;
        for (int i = tid; i < DIM / 4; i += 128) qs4[i] = q4[i];
        for (int i = tid; i < KSEL * (DIM / 4); i += 128) {
            int j = i / (DIM / 4), c = i % (DIM / 4);
            ((float4*)k_s[j])[c] =
                ((const float4*)(Kb + (size_t)idx_s[j] * DIM))[c];
        }
    }
    __syncthreads();

    for (int p = tid; p < HEADS * KSEL; p += 128) {
        int h = p / KSEL, j = p % KSEL;
        float dot = 0.0f;
        #pragma unroll
        for (int d = 0; d < DH; d++)
            dot = fmaf(q_s[h * DH + d], k_s[j][h * DH + d], dot);
        s_s[h][j] = dot * 0.125f;
    }
    __syncthreads();

    if (tid < HEADS) {
        int h = tid;
        float m = s_s[h][0];
        #pragma unroll
        for (int j = 1; j < KSEL; j++) m = fmaxf(m, s_s[h][j]);
        float e[KSEL], sum = 0.0f;
        #pragma unroll
        for (int j = 0; j < KSEL; j++) { e[j] = expf(s_s[h][j] - m); sum += e[j]; }
        float inv = 1.0f / sum;
        #pragma unroll
        for (int j = 0; j < KSEL; j++) s_s[h][j] = e[j] * inv;
    }
    __syncthreads();

    if (tid < KSEL) {
        float m = 0.0f;
        #pragma unroll
        for (int h = 0; h < HEADS; h++) m += s_s[h][tid];
        attn_out[(size_t)b * KSEL + tid] = m * (1.0f / HEADS);
    }

    for (int d = tid; d < DIM; d += 128) {
        int h = d / DH;
        float acc = 0.0f;
        #pragma unroll
        for (int j = 0; j < KSEL; j++)
            acc = fmaf(s_s[h][j], Vb[(size_t)idx_s[j] * DIM + d], acc);
        ctx[(size_t)b * DIM + d] = acc;
    }
}

// ---------------- host launcher -------------------------------------------
extern "C" void kernel_launch(void* const* d_in, const int* in_sizes, int n_in,
                              void* d_out, int out_size) {
    const float* query  = (const float*)d_in[0];
    const float* bank   = (const float*)d_in[1];
    const float* logits = (const float*)d_in[2];
    const float* Wq_proj = (const float*)d_in[3];
    const float* bq_proj = (const float*)d_in[4];
    const float* Wp_proj = (const float*)d_in[5];
    const float* bp_proj = (const float*)d_in[6];
    const float* Wq = (const float*)d_in[7];
    const float* bq = (const float*)d_in[8];
    const float* Wk = (const float*)d_in[9];
    const float* bk = (const float*)d_in[10];
    const float* Wv = (const float*)d_in[11];
    const float* bv = (const float*)d_in[12];
    const float* Wo = (const float*)d_in[13];
    const float* bo = (const float*)d_in[14];

    float* out = (float*)d_out;
    float* out_ctx  = out;
    float* out_attn = out + (size_t)BATCH * DIM;

    float *Wqc, *Wkc, *Wvc, *bqc, *bkc, *bvc, *qh, *Kb, *Vb, *ctx;
    int* topk;
    __nv_bfloat16 *q_hi, *q_lo, *bank_hi, *bank_lo, *ctx_hi, *ctx_lo;
    __nv_bfloat16 *Wqc_hi, *Wqc_lo, *Wkc_hi, *Wkc_lo, *Wvc_hi, *Wvc_lo, *Wo_hi, *Wo_lo;
    cudaGetSymbolAddress((void**)&Wqc, g_Wqc);
    cudaGetSymbolAddress((void**)&Wkc, g_Wkc);
    cudaGetSymbolAddress((void**)&Wvc, g_Wvc);
    cudaGetSymbolAddress((void**)&bqc, g_bqc);
    cudaGetSymbolAddress((void**)&bkc, g_bkc);
    cudaGetSymbolAddress((void**)&bvc, g_bvc);
    cudaGetSymbolAddress((void**)&qh,  g_qh);
    cudaGetSymbolAddress((void**)&Kb,  g_Kb);
    cudaGetSymbolAddress((void**)&Vb,  g_Vb);
    cudaGetSymbolAddress((void**)&ctx, g_ctx);
    cudaGetSymbolAddress((void**)&topk, g_topk);
    cudaGetSymbolAddress((void**)&q_hi, g_q_hi);
    cudaGetSymbolAddress((void**)&q_lo, g_q_lo);
    cudaGetSymbolAddress((void**)&bank_hi, g_bank_hi);
    cudaGetSymbolAddress((void**)&bank_lo, g_bank_lo);
    cudaGetSymbolAddress((void**)&ctx_hi, g_ctx_hi);
    cudaGetSymbolAddress((void**)&ctx_lo, g_ctx_lo);
    cudaGetSymbolAddress((void**)&Wqc_hi, g_Wqc_hi);
    cudaGetSymbolAddress((void**)&Wqc_lo, g_Wqc_lo);
    cudaGetSymbolAddress((void**)&Wkc_hi, g_Wkc_hi);
    cudaGetSymbolAddress((void**)&Wkc_lo, g_Wkc_lo);
    cudaGetSymbolAddress((void**)&Wvc_hi, g_Wvc_hi);
    cudaGetSymbolAddress((void**)&Wvc_lo, g_Wvc_lo);
    cudaGetSymbolAddress((void**)&Wo_hi, g_Wo_hi);
    cudaGetSymbolAddress((void**)&Wo_lo, g_Wo_lo);

    cudaFuncSetAttribute(mma_gemm,
                         cudaFuncAttributeMaxDynamicSharedMemorySize, MMA_SMEM);

    // independent work first
    topk6_kernel<<<BATCH, 256>>>(logits, topk);
    split_kernel<<<BATCH * DIM / 8 / 256, 256>>>(query, q_hi, q_lo);
    split_kernel<<<PROTO * DIM / 8 / 256, 256>>>(bank, bank_hi, bank_lo);
    split_kernel<<<DIM * DIM / 8 / 256, 256>>>(Wo, Wo_hi, Wo_lo);

    // weight combines (FFMA2)
    {
        GemmBatch gb = {};
        gb.A[0] = Wq; gb.A[1] = Wk; gb.A[2] = Wv;
        gb.B[0] = Wq_proj; gb.B[1] = Wp_proj; gb.B[2] = Wp_proj;
        gb.C[0] = Wqc; gb.C[1] = Wkc; gb.C[2] = Wvc;
        gemm_combine<<<dim3(DIM / 128, DIM / 128, 3), 256>>>(gb, DIM, DIM, DIM);
    }
    {
        BiasBatch bb = {};
        bb.W[0] = Wq; bb.W[1] = Wk; bb.W[2] = Wv;
        bb.bin[0] = bq_proj; bb.bin[1] = bp_proj; bb.bin[2] = bp_proj;
        bb.badd[0] = bq; bb.badd[1] = bk; bb.badd[2] = bv;
        bb.out[0] = bqc; bb.out[1] = bkc; bb.out[2] = bvc;
        bias_combine_kernel<<<dim3(DIM / 8, 3), 256>>>(bb);
    }
    split_kernel<<<DIM * DIM / 8 / 256, 256>>>(Wqc, Wqc_hi, Wqc_lo);
    split_kernel<<<DIM * DIM / 8 / 256, 256>>>(Wkc, Wkc_hi, Wkc_lo);
    split_kernel<<<DIM * DIM / 8 / 256, 256>>>(Wvc, Wvc_hi, Wvc_lo);

    // qh = query @ Wqc^T + bqc
    {
        MmaB mb = {};
        mb.Ahi[0] = q_hi; mb.Alo[0] = q_lo;
        mb.Bhi[0] = Wqc_hi; mb.Blo[0] = Wqc_lo;
        mb.bias[0] = bqc; mb.C[0] = qh;
        mma_gemm<<<dim3(DIM / 128, BATCH / 128, 1), 256, MMA_SMEM>>>(mb, BATCH);
    }
    // Kb / Vb batched (shared A)
    {
        MmaB mb = {};
        mb.Ahi[0] = bank_hi; mb.Alo[0] = bank_lo;
        mb.Bhi[0] = Wkc_hi;  mb.Blo[0] = Wkc_lo;
        mb.bias[0] = bkc;    mb.C[0] = Kb;
        mb.Ahi[1] = bank_hi; mb.Alo[1] = bank_lo;
        mb.Bhi[1] = Wvc_hi;  mb.Blo[1] = Wvc_lo;
        mb.bias[1] = bvc;    mb.C[1] = Vb;
        mma_gemm<<<dim3(DIM / 128, PROTO / 128, 2), 256, MMA_SMEM>>>(mb, PROTO);
    }

    // attention
    attention_kernel<<<BATCH, 128>>>(qh, Kb, Vb, topk, ctx, out_attn);

    // out projection
    split_kernel<<<BATCH * DIM / 8 / 256, 256>>>(ctx, ctx_hi, ctx_lo);
    {
        MmaB mb = {};
        mb.Ahi[0] = ctx_hi; mb.Alo[0] = ctx_lo;
        mb.Bhi[0] = Wo_hi;  mb.Blo[0] = Wo_lo;
        mb.bias[0] = bo;    mb.C[0] = out_ctx;
        mma_gemm<<<dim3(DIM / 128, BATCH / 128, 1), 256, MMA_SMEM>>>(mb, BATCH);
    }
}

// round 5
// speedup vs baseline: 3.9428x; 1.3861x over previous
#include <cuda_runtime.h>
#include <cuda_bf16.h>
#include <math.h>

#define BATCH 8192
#define PROTO 4096
#define DIM   1024
#define HEADS 16
#define DH    64
#define KSEL  6

typedef unsigned long long ull;
typedef unsigned int u32;

// ---------------- device scratch ----------------
__device__ float g_Wqc[DIM * DIM];
__device__ float g_Wkc[DIM * DIM];
__device__ float g_Wvc[DIM * DIM];
__device__ float g_bqc[DIM];
__device__ float g_bkc[DIM];
__device__ float g_bvc[DIM];
__device__ float g_qh[BATCH * DIM];
__device__ float g_Kb[PROTO * DIM];
__device__ float g_Vb[PROTO * DIM];
__device__ int   g_topk[BATCH * KSEL];

// bf16 hi/lo splits, row-major [R][DIM]
__device__ __align__(16) __nv_bfloat16 g_q_hi[BATCH * DIM];
__device__ __align__(16) __nv_bfloat16 g_q_lo[BATCH * DIM];
__device__ __align__(16) __nv_bfloat16 g_bank_hi[PROTO * DIM];
__device__ __align__(16) __nv_bfloat16 g_bank_lo[PROTO * DIM];
__device__ __align__(16) __nv_bfloat16 g_ctx_hi[BATCH * DIM];
__device__ __align__(16) __nv_bfloat16 g_ctx_lo[BATCH * DIM];
// raw attention weights split
__device__ __align__(16) __nv_bfloat16 g_Wq_hi[DIM * DIM];
__device__ __align__(16) __nv_bfloat16 g_Wq_lo[DIM * DIM];
__device__ __align__(16) __nv_bfloat16 g_Wk_hi[DIM * DIM];
__device__ __align__(16) __nv_bfloat16 g_Wk_lo[DIM * DIM];
__device__ __align__(16) __nv_bfloat16 g_Wv_hi[DIM * DIM];
__device__ __align__(16) __nv_bfloat16 g_Wv_lo[DIM * DIM];
// transpose-splits of projection weights
__device__ __align__(16) __nv_bfloat16 g_WqpT_hi[DIM * DIM];
__device__ __align__(16) __nv_bfloat16 g_WqpT_lo[DIM * DIM];
__device__ __align__(16) __nv_bfloat16 g_WppT_hi[DIM * DIM];
__device__ __align__(16) __nv_bfloat16 g_WppT_lo[DIM * DIM];
// combined weight splits
__device__ __align__(16) __nv_bfloat16 g_Wqc_hi[DIM * DIM];
__device__ __align__(16) __nv_bfloat16 g_Wqc_lo[DIM * DIM];
__device__ __align__(16) __nv_bfloat16 g_Wkc_hi[DIM * DIM];
__device__ __align__(16) __nv_bfloat16 g_Wkc_lo[DIM * DIM];
__device__ __align__(16) __nv_bfloat16 g_Wvc_hi[DIM * DIM];
__device__ __align__(16) __nv_bfloat16 g_Wvc_lo[DIM * DIM];
__device__ __align__(16) __nv_bfloat16 g_Wo_hi[DIM * DIM];
__device__ __align__(16) __nv_bfloat16 g_Wo_lo[DIM * DIM];

// ---------------- low-level helpers ----------------
__device__ __forceinline__ u32 smem_u32(const void* p) {
    u32 a;
    asm("{ .reg .u64 t; cvta.to.shared.u64 t, %1; cvt.u32.u64 %0, t; }"
        : "=r"(a) : "l"(p));
    return a;
}
__device__ __forceinline__ void cp_async16(u32 dst, const void* src) {
    asm volatile("cp.async.cg.shared.global [%0], [%1], 16;"
                 :: "r"(dst), "l"(src) : "memory");
}
__device__ __forceinline__ void cp_commit() {
    asm volatile("cp.async.commit_group;" ::: "memory");
}
__device__ __forceinline__ void cp_wait2() {
    asm volatile("cp.async.wait_group 2;" ::: "memory");
}
__device__ __forceinline__ void cp_wait1() {
    asm volatile("cp.async.wait_group 1;" ::: "memory");
}
__device__ __forceinline__ void cp_wait0() {
    asm volatile("cp.async.wait_group 0;" ::: "memory");
}
__device__ __forceinline__ void ldsm4(u32* d, u32 addr) {
    asm volatile("ldmatrix.sync.aligned.m8n8.x4.shared.b16 {%0,%1,%2,%3}, [%4];"
                 : "=r"(d[0]), "=r"(d[1]), "=r"(d[2]), "=r"(d[3]) : "r"(addr));
}
__device__ __forceinline__ void mma_bf16(float* c, const u32* a, u32 b0, u32 b1) {
    asm volatile("mma.sync.aligned.m16n8k16.row.col.f32.bf16.bf16.f32 "
                 "{%0,%1,%2,%3},{%4,%5,%6,%7},{%8,%9},{%0,%1,%2,%3};"
                 : "+f"(c[0]), "+f"(c[1]), "+f"(c[2]), "+f"(c[3])
                 : "r"(a[0]), "r"(a[1]), "r"(a[2]), "r"(a[3]), "r"(b0), "r"(b1));
}

// ---------------- split fp32 -> bf16 hi/lo (row-major) ----------------
__global__ void split_kernel(const float* __restrict__ X,
                             __nv_bfloat16* __restrict__ hi,
                             __nv_bfloat16* __restrict__ lo) {
    size_t id = ((size_t)blockIdx.x * 256 + threadIdx.x) * 8;
    const float4* src = (const float4*)(X + id);
    float4 a = src[0], b = src[1];
    float xs[8] = {a.x, a.y, a.z, a.w, b.x, b.y, b.z, b.w};
    __nv_bfloat16 h[8], l[8];
    #pragma unroll
    for (int i = 0; i < 8; i++) {
        h[i] = __float2bfloat16(xs[i]);
        l[i] = __float2bfloat16(xs[i] - __bfloat162float(h[i]));
    }
    *(uint4*)(hi + id) = *(uint4*)h;
    *(uint4*)(lo + id) = *(uint4*)l;
}

// batched version (3 equal-size DIMxDIM matrices via blockIdx.y)
struct Split3 {
    const float* X[3];
    __nv_bfloat16* hi[3];
    __nv_bfloat16* lo[3];
};
__global__ void split3_kernel(Split3 p) {
    const int z = blockIdx.y;
    size_t id = ((size_t)blockIdx.x * 256 + threadIdx.x) * 8;
    const float4* src = (const float4*)(p.X[z] + id);
    float4 a = src[0], b = src[1];
    float xs[8] = {a.x, a.y, a.z, a.w, b.x, b.y, b.z, b.w};
    __nv_bfloat16 h[8], l[8];
    #pragma unroll
    for (int i = 0; i < 8; i++) {
        h[i] = __float2bfloat16(xs[i]);
        l[i] = __float2bfloat16(xs[i] - __bfloat162float(h[i]));
    }
    *(uint4*)(p.hi[z] + id) = *(uint4*)h;
    *(uint4*)(p.lo[z] + id) = *(uint4*)l;
}

// ---------------- transpose-split: T[n][k] = X[k][n], bf16 hi/lo ----------
struct TSplit2 {
    const float* X[2];
    __nv_bfloat16* hi[2];
    __nv_bfloat16* lo[2];
};
__global__ void tsplit_kernel(TSplit2 p) {
    __shared__ float t[32][33];
    const int z = blockIdx.z;
    const float* __restrict__ X = p.X[z];
    const int tx = threadIdx.x & 31, ty = threadIdx.x >> 5;  // 32 x 8
    const int bx = blockIdx.x * 32, by = blockIdx.y * 32;
    #pragma unroll
    for (int i = 0; i < 4; i++)
        t[ty + 8 * i][tx] = X[(size_t)(by + ty + 8 * i) * DIM + bx + tx];
    __syncthreads();
    #pragma unroll
    for (int i = 0; i < 4; i++) {
        float x = t[tx][ty + 8 * i];
        __nv_bfloat16 h = __float2bfloat16(x);
        __nv_bfloat16 l = __float2bfloat16(x - __bfloat162float(h));
        size_t o = (size_t)(bx + ty + 8 * i) * DIM + by + tx;
        p.hi[z][o] = h;
        p.lo[z][o] = l;
    }
}

// ---------------- mma.sync GEMM (bf16x3), flattened multi-job launch ------
// C[M,1024] = A[M,1024] @ B[1024,1024]^T (+ bias). A,B given as hi/lo splits
// (B row-major [n][k]). Tile 128x128x32, 8 warps (4m x 2n), 3-stage cp.async.
#define BK 32
#define SKB 40                        /* bf16 row stride in smem (80 B) */
#define TILE_SM (128 * SKB * 2)       /* 10240 B */
#define STAGE_SM (4 * TILE_SM)        /* 40960 B */
#define MMA_SMEM (3 * STAGE_SM)       /* 122880 B */

struct MmaJob {
    const __nv_bfloat16 *Ahi, *Alo, *Bhi, *Blo;
    const float* bias;
    float* C;
    int prefix;                       /* first flattened block id of this job */
};
struct MmaB {
    MmaJob j[3];
    int nj;
};

__global__ __launch_bounds__(256, 1)
void mma_gemm(MmaB p) {
    extern __shared__ __align__(16) char sm[];
    const u32 sbase = smem_u32(sm);

    const int bid = blockIdx.x;
    int z = 0;
    if (p.nj > 1 && bid >= p.j[1].prefix) z = 1;
    if (p.nj > 2 && bid >= p.j[2].prefix) z = 2;
    const MmaJob& J = p.j[z];
    const int rel = bid - J.prefix;
    const int m0 = (rel >> 3) * 128, n0 = (rel & 7) * 128;

    const __nv_bfloat16* __restrict__ Ahi = J.Ahi;
    const __nv_bfloat16* __restrict__ Alo = J.Alo;
    const __nv_bfloat16* __restrict__ Bhi = J.Bhi;
    const __nv_bfloat16* __restrict__ Blo = J.Blo;

    const int tid = threadIdx.x, lane = tid & 31, wid = tid >> 5;
    const int wm = wid >> 1, wn = wid & 1;

    const int ch0 = tid, ch1 = tid + 256;
    const int lr0 = ch0 >> 2, ls0 = ch0 & 3;
    const int lr1 = ch1 >> 2, ls1 = ch1 & 3;
    const __nv_bfloat16* gA0hi = Ahi + (size_t)(m0 + lr0) * DIM + ls0 * 8;
    const __nv_bfloat16* gA1hi = Ahi + (size_t)(m0 + lr1) * DIM + ls1 * 8;
    const __nv_bfloat16* gA0lo = Alo + (size_t)(m0 + lr0) * DIM + ls0 * 8;
    const __nv_bfloat16* gA1lo = Alo + (size_t)(m0 + lr1) * DIM + ls1 * 8;
    const __nv_bfloat16* gB0hi = Bhi + (size_t)(n0 + lr0) * DIM + ls0 * 8;
    const __nv_bfloat16* gB1hi = Bhi + (size_t)(n0 + lr1) * DIM + ls1 * 8;
    const __nv_bfloat16* gB0lo = Blo + (size_t)(n0 + lr0) * DIM + ls0 * 8;
    const __nv_bfloat16* gB1lo = Blo + (size_t)(n0 + lr1) * DIM + ls1 * 8;
    const u32 d0 = lr0 * (SKB * 2) + ls0 * 16;
    const u32 d1 = lr1 * (SKB * 2) + ls1 * 16;

    #define LOAD_STAGE(s)                                                 \
    do {                                                                  \
        const u32 st_ = sbase + ((s) % 3) * STAGE_SM;                     \
        const int k0_ = (s) * BK;                                         \
        cp_async16(st_ + d0,               gA0hi + k0_);                  \
        cp_async16(st_ + d1,               gA1hi + k0_);                  \
        cp_async16(st_ + TILE_SM + d0,     gA0lo + k0_);                  \
        cp_async16(st_ + TILE_SM + d1,     gA1lo + k0_);                  \
        cp_async16(st_ + 2 * TILE_SM + d0, gB0hi + k0_);                  \
        cp_async16(st_ + 2 * TILE_SM + d1, gB1hi + k0_);                  \
        cp_async16(st_ + 3 * TILE_SM + d0, gB0lo + k0_);                  \
        cp_async16(st_ + 3 * TILE_SM + d1, gB1lo + k0_);                  \
        cp_commit();                                                      \
    } while (0)

    float c[2][8][4];
    #pragma unroll
    for (int i = 0; i < 2; i++)
        #pragma unroll
        for (int j = 0; j < 8; j++)
            #pragma unroll
            for (int q = 0; q < 4; q++) c[i][j][q] = 0.0f;

    const int NS = DIM / BK;   // 32
    LOAD_STAGE(0);
    LOAD_STAGE(1);

    const u32 rowoff = (lane & 15) * (SKB * 2) + (lane >> 4) * 16;

    for (int s = 0; s < NS; s++) {
        if (s + 2 < NS) { LOAD_STAGE(s + 2); cp_wait2(); }
        else if (s + 1 < NS) cp_wait1();
        else cp_wait0();
        __syncthreads();

        const u32 st = sbase + (s % 3) * STAGE_SM;
        const u32 aHiB = st + (wm * 32) * (SKB * 2);
        const u32 aLoB = st + TILE_SM + (wm * 32) * (SKB * 2);
        const u32 bHiB = st + 2 * TILE_SM + (wn * 64) * (SKB * 2);
        const u32 bLoB = st + 3 * TILE_SM + (wn * 64) * (SKB * 2);

        #pragma unroll
        for (int kk = 0; kk < 2; kk++) {
            const u32 ko = kk * 32;   // 16 bf16 = 32 B
            u32 ah[2][4], al[2][4];
            ldsm4(ah[0], aHiB + rowoff + ko);
            ldsm4(ah[1], aHiB + 16 * (SKB * 2) + rowoff + ko);
            ldsm4(al[0], aLoB + rowoff + ko);
            ldsm4(al[1], aLoB + 16 * (SKB * 2) + rowoff + ko);
            u32 bh[4][4], bl[4][4];
            #pragma unroll
            for (int g = 0; g < 4; g++) {
                ldsm4(bh[g], bHiB + g * 16 * (SKB * 2) + rowoff + ko);
                ldsm4(bl[g], bLoB + g * 16 * (SKB * 2) + rowoff + ko);
            }
            #pragma unroll
            for (int mi = 0; mi < 2; mi++)
                #pragma unroll
                for (int g = 0; g < 4; g++)
                    #pragma unroll
                    for (int sub = 0; sub < 2; sub++) {
                        float* cc = c[mi][g * 2 + sub];
                        mma_bf16(cc, ah[mi], bh[g][sub], bh[g][sub + 2]);
                        mma_bf16(cc, ah[mi], bl[g][sub], bl[g][sub + 2]);
                        mma_bf16(cc, al[mi], bh[g][sub], bh[g][sub + 2]);
                    }
        }
        __syncthreads();
    }

    // epilogue
    float* __restrict__ C = J.C;
    const float* __restrict__ bias = J.bias;
    #pragma unroll
    for (int mi = 0; mi < 2; mi++) {
        const int row = m0 + wm * 32 + mi * 16 + (lane >> 2);
        #pragma unroll
        for (int ni = 0; ni < 8; ni++) {
            const int col = n0 + wn * 64 + ni * 8 + 2 * (lane & 3);
            float2 bv = bias ? *(const float2*)(bias + col)
                             : make_float2(0.0f, 0.0f);
            const float* cc = c[mi][ni];
            *(float2*)&C[(size_t)row * DIM + col] =
                make_float2(cc[0] + bv.x, cc[1] + bv.y);
            *(float2*)&C[(size_t)(row + 8) * DIM + col] =
                make_float2(cc[2] + bv.x, cc[3] + bv.y);
        }
    }
    #undef LOAD_STAGE
}

// ---------------- batched bias combine ----------------
struct BiasBatch {
    const float* W[3];
    const float* bin[3];
    const float* badd[3];
    float*       out[3];
};

__global__ void bias_combine_kernel(BiasBatch p) {
    const int z = blockIdx.y;
    const int warp = threadIdx.x >> 5, lane = threadIdx.x & 31;
    const int i = blockIdx.x * 8 + warp;
    const float* __restrict__ row = p.W[z] + (size_t)i * DIM;
    const float* __restrict__ bin = p.bin[z];
    float s = 0.0f;
    for (int t = lane; t < DIM; t += 32) s = fmaf(row[t], bin[t], s);
    #pragma unroll
    for (int o = 16; o; o >>= 1) s += __shfl_down_sync(0xffffffffu, s, o);
    if (lane == 0) p.out[z][i] = s + p.badd[z][i];
}

// ---------------- top-6 per row (register scan + shuffle merge) -----------
__global__ void topk6_kernel(const float* __restrict__ logits,
                             int* __restrict__ topk) {
    const int b = blockIdx.x;
    const int tid = threadIdx.x;   // 256
    const int lane = tid & 31, wid = tid >> 5;
    const float* __restrict__ src = logits + (size_t)b * PROTO;

    float v[KSEL]; int ix[KSEL];
    #pragma unroll
    for (int q = 0; q < KSEL; q++) { v[q] = -INFINITY; ix[q] = 0x7fffffff; }

    #pragma unroll
    for (int pp = 0; pp < PROTO / 256 / 4; pp++) {
        int i = (tid + pp * 256) * 4;
        float4 x4 = *(const float4*)(src + i);
        float xs[4] = {x4.x, x4.y, x4.z, x4.w};
        #pragma unroll
        for (int u = 0; u < 4; u++) {
            float x = xs[u];
            if (x > v[KSEL - 1]) {
                v[KSEL - 1] = x; ix[KSEL - 1] = i + u;
                #pragma unroll
                for (int q = KSEL - 1; q > 0; q--) {
                    if (v[q] > v[q - 1]) {
                        float tv = v[q]; v[q] = v[q - 1]; v[q - 1] = tv;
                        int ti = ix[q]; ix[q] = ix[q - 1]; ix[q - 1] = ti;
                    }
                }
            }
        }
    }

    // per-warp ordered top-6 via 6 argmax rounds (pop-head)
    __shared__ float wv[8][KSEL];
    __shared__ int   wi[8][KSEL];
    #pragma unroll
    for (int t = 0; t < KSEL; t++) {
        float cv = v[0]; int ci = ix[0];
        #pragma unroll
        for (int o = 16; o; o >>= 1) {
            float ov = __shfl_down_sync(0xffffffffu, cv, o);
            int oi = __shfl_down_sync(0xffffffffu, ci, o);
            if (ov > cv || (ov == cv && oi < ci)) { cv = ov; ci = oi; }
        }
        cv = __shfl_sync(0xffffffffu, cv, 0);
        ci = __shfl_sync(0xffffffffu, ci, 0);
        if (lane == 0) { wv[wid][t] = cv; wi[wid][t] = ci; }
        if (ix[0] == ci) {   // pop head
            #pragma unroll
            for (int q = 0; q < KSEL - 1; q++) { v[q] = v[q + 1]; ix[q] = ix[q + 1]; }
            v[KSEL - 1] = -INFINITY; ix[KSEL - 1] = 0x7fffffff;
        }
    }
    __syncthreads();

    // warp 0 merges the 8 warp lists
    if (wid == 0) {
        float lv[KSEL]; int li[KSEL];
        #pragma unroll
        for (int q = 0; q < KSEL; q++) {
            lv[q] = (lane < 8) ? wv[lane][q] : -INFINITY;
            li[q] = (lane < 8) ? wi[lane][q] : 0x7fffffff;
        }
        #pragma unroll
        for (int t = 0; t < KSEL; t++) {
            float cv = lv[0]; int ci = li[0];
            #pragma unroll
            for (int o = 16; o; o >>= 1) {
                float ov = __shfl_down_sync(0xffffffffu, cv, o);
                int oi = __shfl_down_sync(0xffffffffu, ci, o);
                if (ov > cv || (ov == cv && oi < ci)) { cv = ov; ci = oi; }
            }
            cv = __shfl_sync(0xffffffffu, cv, 0);
            ci = __shfl_sync(0xffffffffu, ci, 0);
            if (lane == 0) topk[(size_t)b * KSEL + t] = ci;
            if (li[0] == ci) {
                #pragma unroll
                for (int q = 0; q < KSEL - 1; q++) { lv[q] = lv[q + 1]; li[q] = li[q + 1]; }
                lv[KSEL - 1] = -INFINITY; li[KSEL - 1] = 0x7fffffff;
            }
        }
    }
}

// ---------------- per-row attention (emits ctx hi/lo splits) --------------
__global__ void attention_kernel(const float* __restrict__ qh,
                                 const float* __restrict__ Kb,
                                 const float* __restrict__ Vb,
                                 const int* __restrict__ topk,
                                 __nv_bfloat16* __restrict__ ctx_hi,
                                 __nv_bfloat16* __restrict__ ctx_lo,
                                 float* __restrict__ attn_out) {
    const int b = blockIdx.x;
    const int tid = threadIdx.x;   // 128
    __shared__ float q_s[DIM];
    __shared__ float k_s[KSEL][DIM];
    __shared__ int   idx_s[KSEL];
    __shared__ float s_s[HEADS][KSEL];

    if (tid < KSEL) idx_s[tid] = topk[(size_t)b * KSEL + tid];
    __syncthreads();

    {
        const float4* q4 = (const float4*)(qh + (size_t)b * DIM);
        float4* qs4 = (float4*)q_s;
        for (int i = tid; i < DIM / 4; i += 128) qs4[i] = q4[i];
        for (int i = tid; i < KSEL * (DIM / 4); i += 128) {
            int j = i / (DIM / 4), c = i % (DIM / 4);
            ((float4*)k_s[j])[c] =
                ((const float4*)(Kb + (size_t)idx_s[j] * DIM))[c];
        }
    }
    __syncthreads();

    for (int p = tid; p < HEADS * KSEL; p += 128) {
        int h = p / KSEL, j = p % KSEL;
        float dot = 0.0f;
        #pragma unroll
        for (int d = 0; d < DH; d++)
            dot = fmaf(q_s[h * DH + d], k_s[j][h * DH + d], dot);
        s_s[h][j] = dot * 0.125f;
    }
    __syncthreads();

    if (tid < HEADS) {
        int h = tid;
        float m = s_s[h][0];
        #pragma unroll
        for (int j = 1; j < KSEL; j++) m = fmaxf(m, s_s[h][j]);
        float e[KSEL], sum = 0.0f;
        #pragma unroll
        for (int j = 0; j < KSEL; j++) { e[j] = expf(s_s[h][j] - m); sum += e[j]; }
        float inv = 1.0f / sum;
        #pragma unroll
        for (int j = 0; j < KSEL; j++) s_s[h][j] = e[j] * inv;
    }
    __syncthreads();

    if (tid < KSEL) {
        float m = 0.0f;
        #pragma unroll
        for (int h = 0; h < HEADS; h++) m += s_s[h][tid];
        attn_out[(size_t)b * KSEL + tid] = m * (1.0f / HEADS);
    }

    for (int d = tid; d < DIM; d += 128) {
        int h = d / DH;
        float acc = 0.0f;
        #pragma unroll
        for (int j = 0; j < KSEL; j++)
            acc = fmaf(s_s[h][j], Vb[(size_t)idx_s[j] * DIM + d], acc);
        __nv_bfloat16 hh = __float2bfloat16(acc);
        ctx_hi[(size_t)b * DIM + d] = hh;
        ctx_lo[(size_t)b * DIM + d] =
            __float2bfloat16(acc - __bfloat162float(hh));
    }
}

// ---------------- host launcher -------------------------------------------
extern "C" void kernel_launch(void* const* d_in, const int* in_sizes, int n_in,
                              void* d_out, int out_size) {
    const float* query  = (const float*)d_in[0];
    const float* bank   = (const float*)d_in[1];
    const float* logits = (const float*)d_in[2];
    const float* Wq_proj = (const float*)d_in[3];
    const float* bq_proj = (const float*)d_in[4];
    const float* Wp_proj = (const float*)d_in[5];
    const float* bp_proj = (const float*)d_in[6];
    const float* Wq = (const float*)d_in[7];
    const float* bq = (const float*)d_in[8];
    const float* Wk = (const float*)d_in[9];
    const float* bk = (const float*)d_in[10];
    const float* Wv = (const float*)d_in[11];
    const float* bv = (const float*)d_in[12];
    const float* Wo = (const float*)d_in[13];
    const float* bo = (const float*)d_in[14];

    float* out = (float*)d_out;
    float* out_ctx  = out;
    float* out_attn = out + (size_t)BATCH * DIM;

    float *Wqc, *Wkc, *Wvc, *bqc, *bkc, *bvc, *qh, *Kb, *Vb;
    int* topk;
    cudaGetSymbolAddress((void**)&Wqc, g_Wqc);
    cudaGetSymbolAddress((void**)&Wkc, g_Wkc);
    cudaGetSymbolAddress((void**)&Wvc, g_Wvc);
    cudaGetSymbolAddress((void**)&bqc, g_bqc);
    cudaGetSymbolAddress((void**)&bkc, g_bkc);
    cudaGetSymbolAddress((void**)&bvc, g_bvc);
    cudaGetSymbolAddress((void**)&qh,  g_qh);
    cudaGetSymbolAddress((void**)&Kb,  g_Kb);
    cudaGetSymbolAddress((void**)&Vb,  g_Vb);
    cudaGetSymbolAddress((void**)&topk, g_topk);

    __nv_bfloat16 *q_hi, *q_lo, *bank_hi, *bank_lo, *ctx_hi, *ctx_lo;
    __nv_bfloat16 *Wq_hi, *Wq_lo, *Wk_hi, *Wk_lo, *Wv_hi, *Wv_lo;
    __nv_bfloat16 *WqpT_hi, *WqpT_lo, *WppT_hi, *WppT_lo;
    __nv_bfloat16 *Wqc_hi, *Wqc_lo, *Wkc_hi, *Wkc_lo, *Wvc_hi, *Wvc_lo, *Wo_hi, *Wo_lo;
    cudaGetSymbolAddress((void**)&q_hi, g_q_hi);
    cudaGetSymbolAddress((void**)&q_lo, g_q_lo);
    cudaGetSymbolAddress((void**)&bank_hi, g_bank_hi);
    cudaGetSymbolAddress((void**)&bank_lo, g_bank_lo);
    cudaGetSymbolAddress((void**)&ctx_hi, g_ctx_hi);
    cudaGetSymbolAddress((void**)&ctx_lo, g_ctx_lo);
    cudaGetSymbolAddress((void**)&Wq_hi, g_Wq_hi);
    cudaGetSymbolAddress((void**)&Wq_lo, g_Wq_lo);
    cudaGetSymbolAddress((void**)&Wk_hi, g_Wk_hi);
    cudaGetSymbolAddress((void**)&Wk_lo, g_Wk_lo);
    cudaGetSymbolAddress((void**)&Wv_hi, g_Wv_hi);
    cudaGetSymbolAddress((void**)&Wv_lo, g_Wv_lo);
    cudaGetSymbolAddress((void**)&WqpT_hi, g_WqpT_hi);
    cudaGetSymbolAddress((void**)&WqpT_lo, g_WqpT_lo);
    cudaGetSymbolAddress((void**)&WppT_hi, g_WppT_hi);
    cudaGetSymbolAddress((void**)&WppT_lo, g_WppT_lo);
    cudaGetSymbolAddress((void**)&Wqc_hi, g_Wqc_hi);
    cudaGetSymbolAddress((void**)&Wqc_lo, g_Wqc_lo);
    cudaGetSymbolAddress((void**)&Wkc_hi, g_Wkc_hi);
    cudaGetSymbolAddress((void**)&Wkc_lo, g_Wkc_lo);
    cudaGetSymbolAddress((void**)&Wvc_hi, g_Wvc_hi);
    cudaGetSymbolAddress((void**)&Wvc_lo, g_Wvc_lo);
    cudaGetSymbolAddress((void**)&Wo_hi, g_Wo_hi);
    cudaGetSymbolAddress((void**)&Wo_lo, g_Wo_lo);

    cudaFuncSetAttribute(mma_gemm,
                         cudaFuncAttributeMaxDynamicSharedMemorySize, MMA_SMEM);

    // independent work first
    topk6_kernel<<<BATCH, 256>>>(logits, topk);
    split_kernel<<<BATCH * DIM / 8 / 256, 256>>>(query, q_hi, q_lo);
    split_kernel<<<PROTO * DIM / 8 / 256, 256>>>(bank, bank_hi, bank_lo);
    split_kernel<<<DIM * DIM / 8 / 256, 256>>>(Wo, Wo_hi, Wo_lo);

    // splits for the combine GEMMs
    {
        Split3 s = {};
        s.X[0] = Wq; s.X[1] = Wk; s.X[2] = Wv;
        s.hi[0] = Wq_hi; s.hi[1] = Wk_hi; s.hi[2] = Wv_hi;
        s.lo[0] = Wq_lo; s.lo[1] = Wk_lo; s.lo[2] = Wv_lo;
        split3_kernel<<<dim3(DIM * DIM / 8 / 256, 3), 256>>>(s);
    }
    {
        TSplit2 t = {};
        t.X[0] = Wq_proj; t.X[1] = Wp_proj;
        t.hi[0] = WqpT_hi; t.hi[1] = WppT_hi;
        t.lo[0] = WqpT_lo; t.lo[1] = WppT_lo;
        tsplit_kernel<<<dim3(32, 32, 2), 256>>>(t);
    }
    {
        BiasBatch bb = {};
        bb.W[0] = Wq; bb.W[1] = Wk; bb.W[2] = Wv;
        bb.bin[0] = bq_proj; bb.bin[1] = bp_proj; bb.bin[2] = bp_proj;
        bb.badd[0] = bq; bb.badd[1] = bk; bb.badd[2] = bv;
        bb.out[0] = bqc; bb.out[1] = bkc; bb.out[2] = bvc;
        bias_combine_kernel<<<dim3(DIM / 8, 3), 256>>>(bb);
    }

    // weight combines on tensor cores: Wqc = Wq @ Wq_proj etc.
    {
        MmaB mb = {};
        mb.nj = 3;
        mb.j[0] = {Wq_hi, Wq_lo, WqpT_hi, WqpT_lo, nullptr, Wqc, 0};
        mb.j[1] = {Wk_hi, Wk_lo, WppT_hi, WppT_lo, nullptr, Wkc, 64};
        mb.j[2] = {Wv_hi, Wv_lo, WppT_hi, WppT_lo, nullptr, Wvc, 128};
        mma_gemm<<<192, 256, MMA_SMEM>>>(mb);
    }
    {
        Split3 s = {};
        s.X[0] = Wqc; s.X[1] = Wkc; s.X[2] = Wvc;
        s.hi[0] = Wqc_hi; s.hi[1] = Wkc_hi; s.hi[2] = Wvc_hi;
        s.lo[0] = Wqc_lo; s.lo[1] = Wkc_lo; s.lo[2] = Wvc_lo;
        split3_kernel<<<dim3(DIM * DIM / 8 / 256, 3), 256>>>(s);
    }

    // merged big GEMMs: qh (512 blocks), Kb (256), Vb (256)
    {
        MmaB mb = {};
        mb.nj = 3;
        mb.j[0] = {q_hi, q_lo, Wqc_hi, Wqc_lo, bqc, qh, 0};
        mb.j[1] = {bank_hi, bank_lo, Wkc_hi, Wkc_lo, bkc, Kb, 512};
        mb.j[2] = {bank_hi, bank_lo, Wvc_hi, Wvc_lo, bvc, Vb, 768};
        mma_gemm<<<1024, 256, MMA_SMEM>>>(mb);
    }

    // attention (emits ctx splits)
    attention_kernel<<<BATCH, 128>>>(qh, Kb, Vb, topk, ctx_hi, ctx_lo, out_attn);

    // out projection
    {
        MmaB mb = {};
        mb.nj = 1;
        mb.j[0] = {ctx_hi, ctx_lo, Wo_hi, Wo_lo, bo, out_ctx, 0};
        mma_gemm<<<512, 256, MMA_SMEM>>>(mb);
    }
}

// round 6
// speedup vs baseline: 4.0751x; 1.0336x over previous
#include <cuda_runtime.h>
#include <cuda_bf16.h>
#include <math.h>

#define BATCH 8192
#define PROTO 4096
#define DIM   1024
#define HEADS 16
#define DH    64
#define KSEL  6

typedef unsigned long long ull;
typedef unsigned int u32;

// ---------------- device scratch ----------------
__device__ float g_bqc[DIM];
__device__ float g_bkc[DIM];
__device__ float g_bvc[DIM];
__device__ float g_qh[BATCH * DIM];
__device__ float g_Kb[PROTO * DIM];
__device__ float g_Vb[PROTO * DIM];
__device__ int   g_topk[BATCH * KSEL];

// bf16 hi/lo splits, row-major [R][DIM]
__device__ __align__(16) __nv_bfloat16 g_q_hi[BATCH * DIM];
__device__ __align__(16) __nv_bfloat16 g_q_lo[BATCH * DIM];
__device__ __align__(16) __nv_bfloat16 g_bank_hi[PROTO * DIM];
__device__ __align__(16) __nv_bfloat16 g_bank_lo[PROTO * DIM];
__device__ __align__(16) __nv_bfloat16 g_ctx_hi[BATCH * DIM];
__device__ __align__(16) __nv_bfloat16 g_ctx_lo[BATCH * DIM];
__device__ __align__(16) __nv_bfloat16 g_Wq_hi[DIM * DIM];
__device__ __align__(16) __nv_bfloat16 g_Wq_lo[DIM * DIM];
__device__ __align__(16) __nv_bfloat16 g_Wk_hi[DIM * DIM];
__device__ __align__(16) __nv_bfloat16 g_Wk_lo[DIM * DIM];
__device__ __align__(16) __nv_bfloat16 g_Wv_hi[DIM * DIM];
__device__ __align__(16) __nv_bfloat16 g_Wv_lo[DIM * DIM];
__device__ __align__(16) __nv_bfloat16 g_WqpT_hi[DIM * DIM];
__device__ __align__(16) __nv_bfloat16 g_WqpT_lo[DIM * DIM];
__device__ __align__(16) __nv_bfloat16 g_WppT_hi[DIM * DIM];
__device__ __align__(16) __nv_bfloat16 g_WppT_lo[DIM * DIM];
__device__ __align__(16) __nv_bfloat16 g_Wqc_hi[DIM * DIM];
__device__ __align__(16) __nv_bfloat16 g_Wqc_lo[DIM * DIM];
__device__ __align__(16) __nv_bfloat16 g_Wkc_hi[DIM * DIM];
__device__ __align__(16) __nv_bfloat16 g_Wkc_lo[DIM * DIM];
__device__ __align__(16) __nv_bfloat16 g_Wvc_hi[DIM * DIM];
__device__ __align__(16) __nv_bfloat16 g_Wvc_lo[DIM * DIM];
__device__ __align__(16) __nv_bfloat16 g_Wo_hi[DIM * DIM];
__device__ __align__(16) __nv_bfloat16 g_Wo_lo[DIM * DIM];

// ---------------- low-level helpers ----------------
__device__ __forceinline__ u32 smem_u32(const void* p) {
    u32 a;
    asm("{ .reg .u64 t; cvta.to.shared.u64 t, %1; cvt.u32.u64 %0, t; }"
        : "=r"(a) : "l"(p));
    return a;
}
__device__ __forceinline__ void cp_async16(u32 dst, const void* src) {
    asm volatile("cp.async.cg.shared.global [%0], [%1], 16;"
                 :: "r"(dst), "l"(src) : "memory");
}
__device__ __forceinline__ void cp_commit() {
    asm volatile("cp.async.commit_group;" ::: "memory");
}
__device__ __forceinline__ void cp_wait3() {
    asm volatile("cp.async.wait_group 3;" ::: "memory");
}
__device__ __forceinline__ void cp_wait2() {
    asm volatile("cp.async.wait_group 2;" ::: "memory");
}
__device__ __forceinline__ void cp_wait1() {
    asm volatile("cp.async.wait_group 1;" ::: "memory");
}
__device__ __forceinline__ void cp_wait0() {
    asm volatile("cp.async.wait_group 0;" ::: "memory");
}
__device__ __forceinline__ void ldsm4(u32* d, u32 addr) {
    asm volatile("ldmatrix.sync.aligned.m8n8.x4.shared.b16 {%0,%1,%2,%3}, [%4];"
                 : "=r"(d[0]), "=r"(d[1]), "=r"(d[2]), "=r"(d[3]) : "r"(addr));
}
__device__ __forceinline__ void mma_bf16(float* c, const u32* a, u32 b0, u32 b1) {
    asm volatile("mma.sync.aligned.m16n8k16.row.col.f32.bf16.bf16.f32 "
                 "{%0,%1,%2,%3},{%4,%5,%6,%7},{%8,%9},{%0,%1,%2,%3};"
                 : "+f"(c[0]), "+f"(c[1]), "+f"(c[2]), "+f"(c[3])
                 : "r"(a[0]), "r"(a[1]), "r"(a[2]), "r"(a[3]), "r"(b0), "r"(b1));
}
__device__ __forceinline__ u32 pack_bf16(float x, float y) {
    __nv_bfloat162 p = __floats2bfloat162_rn(x, y);
    return *(u32*)&p;
}

// ---------------- flattened split: fp32 -> bf16 hi/lo, 6 jobs -------------
struct SplitAll {
    const float* X[6];
    __nv_bfloat16* hi[6];
    __nv_bfloat16* lo[6];
    int prefix[6];
};
__global__ void split_all_kernel(SplitAll p) {
    const int bid = blockIdx.x;
    int z = 0;
    #pragma unroll
    for (int q = 1; q < 6; q++) if (bid >= p.prefix[q]) z = q;
    size_t id = (((size_t)(bid - p.prefix[z])) * 256 + threadIdx.x) * 8;
    const float4* src = (const float4*)(p.X[z] + id);
    float4 a = src[0], b = src[1];
    float xs[8] = {a.x, a.y, a.z, a.w, b.x, b.y, b.z, b.w};
    __nv_bfloat16 h[8], l[8];
    #pragma unroll
    for (int i = 0; i < 8; i++) {
        h[i] = __float2bfloat16(xs[i]);
        l[i] = __float2bfloat16(xs[i] - __bfloat162float(h[i]));
    }
    *(uint4*)(p.hi[z] + id) = *(uint4*)h;
    *(uint4*)(p.lo[z] + id) = *(uint4*)l;
}

// ---------------- transpose-split: T[n][k] = X[k][n], bf16 hi/lo ----------
struct TSplit2 {
    const float* X[2];
    __nv_bfloat16* hi[2];
    __nv_bfloat16* lo[2];
};
__global__ void tsplit_kernel(TSplit2 p) {
    __shared__ float t[32][33];
    const int z = blockIdx.z;
    const float* __restrict__ X = p.X[z];
    const int tx = threadIdx.x & 31, ty = threadIdx.x >> 5;  // 32 x 8
    const int bx = blockIdx.x * 32, by = blockIdx.y * 32;
    #pragma unroll
    for (int i = 0; i < 4; i++)
        t[ty + 8 * i][tx] = X[(size_t)(by + ty + 8 * i) * DIM + bx + tx];
    __syncthreads();
    #pragma unroll
    for (int i = 0; i < 4; i++) {
        float x = t[tx][ty + 8 * i];
        __nv_bfloat16 h = __float2bfloat16(x);
        __nv_bfloat16 l = __float2bfloat16(x - __bfloat162float(h));
        size_t o = (size_t)(bx + ty + 8 * i) * DIM + by + tx;
        p.hi[z][o] = h;
        p.lo[z][o] = l;
    }
}

// ---------------- mma.sync GEMM (bf16x3), flattened multi-job launch ------
// Tile 128x128x32, 8 warps (4m x 2n), 4-stage cp.async pipeline.
// Epilogue: fp32 C (+bias) OR direct bf16 hi/lo split output.
#define BK 32
#define SKB 40                        /* bf16 row stride in smem (80 B) */
#define TILE_SM (128 * SKB * 2)       /* 10240 B */
#define STAGE_SM (4 * TILE_SM)        /* 40960 B */
#define MMA_SMEM (4 * STAGE_SM)       /* 163840 B */

struct MmaJob {
    const __nv_bfloat16 *Ahi, *Alo, *Bhi, *Blo;
    const float* bias;
    float* C;                          /* fp32 output (or null) */
    __nv_bfloat16 *Chi, *Clo;          /* bf16 split output (or null) */
    int prefix;
};
struct MmaB {
    MmaJob j[3];
    int nj;
};

__global__ __launch_bounds__(256, 1)
void mma_gemm(MmaB p) {
    extern __shared__ __align__(16) char sm[];
    const u32 sbase = smem_u32(sm);

    const int bid = blockIdx.x;
    int z = 0;
    if (p.nj > 1 && bid >= p.j[1].prefix) z = 1;
    if (p.nj > 2 && bid >= p.j[2].prefix) z = 2;
    const MmaJob& J = p.j[z];
    const int rel = bid - J.prefix;
    const int m0 = (rel >> 3) * 128, n0 = (rel & 7) * 128;

    const __nv_bfloat16* __restrict__ Ahi = J.Ahi;
    const __nv_bfloat16* __restrict__ Alo = J.Alo;
    const __nv_bfloat16* __restrict__ Bhi = J.Bhi;
    const __nv_bfloat16* __restrict__ Blo = J.Blo;

    const int tid = threadIdx.x, lane = tid & 31, wid = tid >> 5;
    const int wm = wid >> 1, wn = wid & 1;

    const int ch0 = tid, ch1 = tid + 256;
    const int lr0 = ch0 >> 2, ls0 = ch0 & 3;
    const int lr1 = ch1 >> 2, ls1 = ch1 & 3;
    const __nv_bfloat16* gA0hi = Ahi + (size_t)(m0 + lr0) * DIM + ls0 * 8;
    const __nv_bfloat16* gA1hi = Ahi + (size_t)(m0 + lr1) * DIM + ls1 * 8;
    const __nv_bfloat16* gA0lo = Alo + (size_t)(m0 + lr0) * DIM + ls0 * 8;
    const __nv_bfloat16* gA1lo = Alo + (size_t)(m0 + lr1) * DIM + ls1 * 8;
    const __nv_bfloat16* gB0hi = Bhi + (size_t)(n0 + lr0) * DIM + ls0 * 8;
    const __nv_bfloat16* gB1hi = Bhi + (size_t)(n0 + lr1) * DIM + ls1 * 8;
    const __nv_bfloat16* gB0lo = Blo + (size_t)(n0 + lr0) * DIM + ls0 * 8;
    const __nv_bfloat16* gB1lo = Blo + (size_t)(n0 + lr1) * DIM + ls1 * 8;
    const u32 d0 = lr0 * (SKB * 2) + ls0 * 16;
    const u32 d1 = lr1 * (SKB * 2) + ls1 * 16;

    #define LOAD_STAGE(s)                                                 \
    do {                                                                  \
        const u32 st_ = sbase + ((s) & 3) * STAGE_SM;                     \
        const int k0_ = (s) * BK;                                         \
        cp_async16(st_ + d0,               gA0hi + k0_);                  \
        cp_async16(st_ + d1,               gA1hi + k0_);                  \
        cp_async16(st_ + TILE_SM + d0,     gA0lo + k0_);                  \
        cp_async16(st_ + TILE_SM + d1,     gA1lo + k0_);                  \
        cp_async16(st_ + 2 * TILE_SM + d0, gB0hi + k0_);                  \
        cp_async16(st_ + 2 * TILE_SM + d1, gB1hi + k0_);                  \
        cp_async16(st_ + 3 * TILE_SM + d0, gB0lo + k0_);                  \
        cp_async16(st_ + 3 * TILE_SM + d1, gB1lo + k0_);                  \
        cp_commit();                                                      \
    } while (0)

    float c[2][8][4];
    #pragma unroll
    for (int i = 0; i < 2; i++)
        #pragma unroll
        for (int j = 0; j < 8; j++)
            #pragma unroll
            for (int q = 0; q < 4; q++) c[i][j][q] = 0.0f;

    const int NS = DIM / BK;   // 32
    LOAD_STAGE(0);
    LOAD_STAGE(1);
    LOAD_STAGE(2);

    const u32 rowoff = (lane & 15) * (SKB * 2) + (lane >> 4) * 16;

    for (int s = 0; s < NS; s++) {
        if (s + 3 < NS) { LOAD_STAGE(s + 3); cp_wait3(); }
        else if (s + 2 < NS) cp_wait2();
        else if (s + 1 < NS) cp_wait1();
        else cp_wait0();
        __syncthreads();

        const u32 st = sbase + (s & 3) * STAGE_SM;
        const u32 aHiB = st + (wm * 32) * (SKB * 2);
        const u32 aLoB = st + TILE_SM + (wm * 32) * (SKB * 2);
        const u32 bHiB = st + 2 * TILE_SM + (wn * 64) * (SKB * 2);
        const u32 bLoB = st + 3 * TILE_SM + (wn * 64) * (SKB * 2);

        #pragma unroll
        for (int kk = 0; kk < 2; kk++) {
            const u32 ko = kk * 32;   // 16 bf16 = 32 B
            u32 ah[2][4], al[2][4];
            ldsm4(ah[0], aHiB + rowoff + ko);
            ldsm4(ah[1], aHiB + 16 * (SKB * 2) + rowoff + ko);
            ldsm4(al[0], aLoB + rowoff + ko);
            ldsm4(al[1], aLoB + 16 * (SKB * 2) + rowoff + ko);
            u32 bh[4][4], bl[4][4];
            #pragma unroll
            for (int g = 0; g < 4; g++) {
                ldsm4(bh[g], bHiB + g * 16 * (SKB * 2) + rowoff + ko);
                ldsm4(bl[g], bLoB + g * 16 * (SKB * 2) + rowoff + ko);
            }
            #pragma unroll
            for (int mi = 0; mi < 2; mi++)
                #pragma unroll
                for (int g = 0; g < 4; g++)
                    #pragma unroll
                    for (int sub = 0; sub < 2; sub++) {
                        float* cc = c[mi][g * 2 + sub];
                        mma_bf16(cc, ah[mi], bh[g][sub], bh[g][sub + 2]);
                        mma_bf16(cc, ah[mi], bl[g][sub], bl[g][sub + 2]);
                        mma_bf16(cc, al[mi], bh[g][sub], bh[g][sub + 2]);
                    }
        }
        __syncthreads();
    }

    // epilogue
    if (J.C) {
        float* __restrict__ C = J.C;
        const float* __restrict__ bias = J.bias;
        #pragma unroll
        for (int mi = 0; mi < 2; mi++) {
            const int row = m0 + wm * 32 + mi * 16 + (lane >> 2);
            #pragma unroll
            for (int ni = 0; ni < 8; ni++) {
                const int col = n0 + wn * 64 + ni * 8 + 2 * (lane & 3);
                float2 bv = bias ? *(const float2*)(bias + col)
                                 : make_float2(0.0f, 0.0f);
                const float* cc = c[mi][ni];
                *(float2*)&C[(size_t)row * DIM + col] =
                    make_float2(cc[0] + bv.x, cc[1] + bv.y);
                *(float2*)&C[(size_t)(row + 8) * DIM + col] =
                    make_float2(cc[2] + bv.x, cc[3] + bv.y);
            }
        }
    } else {
        __nv_bfloat16* __restrict__ Chi = J.Chi;
        __nv_bfloat16* __restrict__ Clo = J.Clo;
        #pragma unroll
        for (int mi = 0; mi < 2; mi++) {
            const int row = m0 + wm * 32 + mi * 16 + (lane >> 2);
            #pragma unroll
            for (int ni = 0; ni < 8; ni++) {
                const int col = n0 + wn * 64 + ni * 8 + 2 * (lane & 3);
                const float* cc = c[mi][ni];
                #pragma unroll
                for (int rr = 0; rr < 2; rr++) {
                    float x0 = cc[rr * 2], x1 = cc[rr * 2 + 1];
                    __nv_bfloat16 h0 = __float2bfloat16(x0);
                    __nv_bfloat16 h1 = __float2bfloat16(x1);
                    float l0 = x0 - __bfloat162float(h0);
                    float l1 = x1 - __bfloat162float(h1);
                    size_t o = (size_t)(row + rr * 8) * DIM + col;
                    __nv_bfloat162 hp; hp.x = h0; hp.y = h1;
                    *(u32*)&Chi[o] = *(u32*)&hp;
                    *(u32*)&Clo[o] = pack_bf16(l0, l1);
                }
            }
        }
    }
    #undef LOAD_STAGE
}

// ---------------- batched bias combine ----------------
struct BiasBatch {
    const float* W[3];
    const float* bin[3];
    const float* badd[3];
    float*       out[3];
};

__global__ void bias_combine_kernel(BiasBatch p) {
    const int z = blockIdx.y;
    const int warp = threadIdx.x >> 5, lane = threadIdx.x & 31;
    const int i = blockIdx.x * 8 + warp;
    const float* __restrict__ row = p.W[z] + (size_t)i * DIM;
    const float* __restrict__ bin = p.bin[z];
    float s = 0.0f;
    for (int t = lane; t < DIM; t += 32) s = fmaf(row[t], bin[t], s);
    #pragma unroll
    for (int o = 16; o; o >>= 1) s += __shfl_down_sync(0xffffffffu, s, o);
    if (lane == 0) p.out[z][i] = s + p.badd[z][i];
}

// ---------------- top-6 per row (register scan + shuffle merge) -----------
__global__ void topk6_kernel(const float* __restrict__ logits,
                             int* __restrict__ topk) {
    const int b = blockIdx.x;
    const int tid = threadIdx.x;   // 256
    const int lane = tid & 31, wid = tid >> 5;
    const float* __restrict__ src = logits + (size_t)b * PROTO;

    float v[KSEL]; int ix[KSEL];
    #pragma unroll
    for (int q = 0; q < KSEL; q++) { v[q] = -INFINITY; ix[q] = 0x7fffffff; }

    #pragma unroll
    for (int pp = 0; pp < PROTO / 256 / 4; pp++) {
        int i = (tid + pp * 256) * 4;
        float4 x4 = *(const float4*)(src + i);
        float xs[4] = {x4.x, x4.y, x4.z, x4.w};
        #pragma unroll
        for (int u = 0; u < 4; u++) {
            float x = xs[u];
            if (x > v[KSEL - 1]) {
                v[KSEL - 1] = x; ix[KSEL - 1] = i + u;
                #pragma unroll
                for (int q = KSEL - 1; q > 0; q--) {
                    if (v[q] > v[q - 1]) {
                        float tv = v[q]; v[q] = v[q - 1]; v[q - 1] = tv;
                        int ti = ix[q]; ix[q] = ix[q - 1]; ix[q - 1] = ti;
                    }
                }
            }
        }
    }

    __shared__ float wv[8][KSEL];
    __shared__ int   wi[8][KSEL];
    #pragma unroll
    for (int t = 0; t < KSEL; t++) {
        float cv = v[0]; int ci = ix[0];
        #pragma unroll
        for (int o = 16; o; o >>= 1) {
            float ov = __shfl_down_sync(0xffffffffu, cv, o);
            int oi = __shfl_down_sync(0xffffffffu, ci, o);
            if (ov > cv || (ov == cv && oi < ci)) { cv = ov; ci = oi; }
        }
        cv = __shfl_sync(0xffffffffu, cv, 0);
        ci = __shfl_sync(0xffffffffu, ci, 0);
        if (lane == 0) { wv[wid][t] = cv; wi[wid][t] = ci; }
        if (ix[0] == ci) {
            #pragma unroll
            for (int q = 0; q < KSEL - 1; q++) { v[q] = v[q + 1]; ix[q] = ix[q + 1]; }
            v[KSEL - 1] = -INFINITY; ix[KSEL - 1] = 0x7fffffff;
        }
    }
    __syncthreads();

    if (wid == 0) {
        float lv[KSEL]; int li[KSEL];
        #pragma unroll
        for (int q = 0; q < KSEL; q++) {
            lv[q] = (lane < 8) ? wv[lane][q] : -INFINITY;
            li[q] = (lane < 8) ? wi[lane][q] : 0x7fffffff;
        }
        #pragma unroll
        for (int t = 0; t < KSEL; t++) {
            float cv = lv[0]; int ci = li[0];
            #pragma unroll
            for (int o = 16; o; o >>= 1) {
                float ov = __shfl_down_sync(0xffffffffu, cv, o);
                int oi = __shfl_down_sync(0xffffffffu, ci, o);
                if (ov > cv || (ov == cv && oi < ci)) { cv = ov; ci = oi; }
            }
            cv = __shfl_sync(0xffffffffu, cv, 0);
            ci = __shfl_sync(0xffffffffu, ci, 0);
            if (lane == 0) topk[(size_t)b * KSEL + t] = ci;
            if (li[0] == ci) {
                #pragma unroll
                for (int q = 0; q < KSEL - 1; q++) { lv[q] = lv[q + 1]; li[q] = li[q + 1]; }
                lv[KSEL - 1] = -INFINITY; li[KSEL - 1] = 0x7fffffff;
            }
        }
    }
}

// ---------------- per-row attention (emits ctx hi/lo splits) --------------
__global__ void attention_kernel(const float* __restrict__ qh,
                                 const float* __restrict__ Kb,
                                 const float* __restrict__ Vb,
                                 const int* __restrict__ topk,
                                 __nv_bfloat16* __restrict__ ctx_hi,
                                 __nv_bfloat16* __restrict__ ctx_lo,
                                 float* __restrict__ attn_out) {
    const int b = blockIdx.x;
    const int tid = threadIdx.x;   // 128
    __shared__ float q_s[DIM];
    __shared__ float k_s[KSEL][DIM];
    __shared__ int   idx_s[KSEL];
    __shared__ float s_s[HEADS][KSEL];

    if (tid < KSEL) idx_s[tid] = topk[(size_t)b * KSEL + tid];
    __syncthreads();

    {
        const float4* q4 = (const float4*)(qh + (size_t)b * DIM);
        float4* qs4 = (float4*)q_s;
        for (int i = tid; i < DIM / 4; i += 128) qs4[i] = q4[i];
        for (int i = tid; i < KSEL * (DIM / 4); i += 128) {
            int j = i / (DIM / 4), c = i % (DIM / 4);
            ((float4*)k_s[j])[c] =
                ((const float4*)(Kb + (size_t)idx_s[j] * DIM))[c];
        }
    }
    __syncthreads();

    for (int p = tid; p < HEADS * KSEL; p += 128) {
        int h = p / KSEL, j = p % KSEL;
        float dot = 0.0f;
        #pragma unroll
        for (int d = 0; d < DH; d++)
            dot = fmaf(q_s[h * DH + d], k_s[j][h * DH + d], dot);
        s_s[h][j] = dot * 0.125f;
    }
    __syncthreads();

    if (tid < HEADS) {
        int h = tid;
        float m = s_s[h][0];
        #pragma unroll
        for (int j = 1; j < KSEL; j++) m = fmaxf(m, s_s[h][j]);
        float e[KSEL], sum = 0.0f;
        #pragma unroll
        for (int j = 0; j < KSEL; j++) { e[j] = expf(s_s[h][j] - m); sum += e[j]; }
        float inv = 1.0f / sum;
        #pragma unroll
        for (int j = 0; j < KSEL; j++) s_s[h][j] = e[j] * inv;
    }
    __syncthreads();

    if (tid < KSEL) {
        float m = 0.0f;
        #pragma unroll
        for (int h = 0; h < HEADS; h++) m += s_s[h][tid];
        attn_out[(size_t)b * KSEL + tid] = m * (1.0f / HEADS);
    }

    for (int d = tid; d < DIM; d += 128) {
        int h = d / DH;
        float acc = 0.0f;
        #pragma unroll
        for (int j = 0; j < KSEL; j++)
            acc = fmaf(s_s[h][j], Vb[(size_t)idx_s[j] * DIM + d], acc);
        __nv_bfloat16 hh = __float2bfloat16(acc);
        ctx_hi[(size_t)b * DIM + d] = hh;
        ctx_lo[(size_t)b * DIM + d] =
            __float2bfloat16(acc - __bfloat162float(hh));
    }
}

// ---------------- host launcher -------------------------------------------
extern "C" void kernel_launch(void* const* d_in, const int* in_sizes, int n_in,
                              void* d_out, int out_size) {
    const float* query  = (const float*)d_in[0];
    const float* bank   = (const float*)d_in[1];
    const float* logits = (const float*)d_in[2];
    const float* Wq_proj = (const float*)d_in[3];
    const float* bq_proj = (const float*)d_in[4];
    const float* Wp_proj = (const float*)d_in[5];
    const float* bp_proj = (const float*)d_in[6];
    const float* Wq = (const float*)d_in[7];
    const float* bq = (const float*)d_in[8];
    const float* Wk = (const float*)d_in[9];
    const float* bk = (const float*)d_in[10];
    const float* Wv = (const float*)d_in[11];
    const float* bv = (const float*)d_in[12];
    const float* Wo = (const float*)d_in[13];
    const float* bo = (const float*)d_in[14];

    float* out = (float*)d_out;
    float* out_ctx  = out;
    float* out_attn = out + (size_t)BATCH * DIM;

    float *bqc, *bkc, *bvc, *qh, *Kb, *Vb;
    int* topk;
    cudaGetSymbolAddress((void**)&bqc, g_bqc);
    cudaGetSymbolAddress((void**)&bkc, g_bkc);
    cudaGetSymbolAddress((void**)&bvc, g_bvc);
    cudaGetSymbolAddress((void**)&qh,  g_qh);
    cudaGetSymbolAddress((void**)&Kb,  g_Kb);
    cudaGetSymbolAddress((void**)&Vb,  g_Vb);
    cudaGetSymbolAddress((void**)&topk, g_topk);

    __nv_bfloat16 *q_hi, *q_lo, *bank_hi, *bank_lo, *ctx_hi, *ctx_lo;
    __nv_bfloat16 *Wq_hi, *Wq_lo, *Wk_hi, *Wk_lo, *Wv_hi, *Wv_lo;
    __nv_bfloat16 *WqpT_hi, *WqpT_lo, *WppT_hi, *WppT_lo;
    __nv_bfloat16 *Wqc_hi, *Wqc_lo, *Wkc_hi, *Wkc_lo, *Wvc_hi, *Wvc_lo, *Wo_hi, *Wo_lo;
    cudaGetSymbolAddress((void**)&q_hi, g_q_hi);
    cudaGetSymbolAddress((void**)&q_lo, g_q_lo);
    cudaGetSymbolAddress((void**)&bank_hi, g_bank_hi);
    cudaGetSymbolAddress((void**)&bank_lo, g_bank_lo);
    cudaGetSymbolAddress((void**)&ctx_hi, g_ctx_hi);
    cudaGetSymbolAddress((void**)&ctx_lo, g_ctx_lo);
    cudaGetSymbolAddress((void**)&Wq_hi, g_Wq_hi);
    cudaGetSymbolAddress((void**)&Wq_lo, g_Wq_lo);
    cudaGetSymbolAddress((void**)&Wk_hi, g_Wk_hi);
    cudaGetSymbolAddress((void**)&Wk_lo, g_Wk_lo);
    cudaGetSymbolAddress((void**)&Wv_hi, g_Wv_hi);
    cudaGetSymbolAddress((void**)&Wv_lo, g_Wv_lo);
    cudaGetSymbolAddress((void**)&WqpT_hi, g_WqpT_hi);
    cudaGetSymbolAddress((void**)&WqpT_lo, g_WqpT_lo);
    cudaGetSymbolAddress((void**)&WppT_hi, g_WppT_hi);
    cudaGetSymbolAddress((void**)&WppT_lo, g_WppT_lo);
    cudaGetSymbolAddress((void**)&Wqc_hi, g_Wqc_hi);
    cudaGetSymbolAddress((void**)&Wqc_lo, g_Wqc_lo);
    cudaGetSymbolAddress((void**)&Wkc_hi, g_Wkc_hi);
    cudaGetSymbolAddress((void**)&Wkc_lo, g_Wkc_lo);
    cudaGetSymbolAddress((void**)&Wvc_hi, g_Wvc_hi);
    cudaGetSymbolAddress((void**)&Wvc_lo, g_Wvc_lo);
    cudaGetSymbolAddress((void**)&Wo_hi, g_Wo_hi);
    cudaGetSymbolAddress((void**)&Wo_lo, g_Wo_lo);

    cudaFuncSetAttribute(mma_gemm,
                         cudaFuncAttributeMaxDynamicSharedMemorySize, MMA_SMEM);

    // #1 topk (independent)
    topk6_kernel<<<BATCH, 256>>>(logits, topk);

    // #2 all row-splits in one launch: query, bank, Wo, Wq, Wk, Wv
    {
        SplitAll s = {};
        s.X[0] = query; s.hi[0] = q_hi;    s.lo[0] = q_lo;    s.prefix[0] = 0;
        s.X[1] = bank;  s.hi[1] = bank_hi; s.lo[1] = bank_lo; s.prefix[1] = 4096;
        s.X[2] = Wo;    s.hi[2] = Wo_hi;   s.lo[2] = Wo_lo;   s.prefix[2] = 6144;
        s.X[3] = Wq;    s.hi[3] = Wq_hi;   s.lo[3] = Wq_lo;   s.prefix[3] = 6656;
        s.X[4] = Wk;    s.hi[4] = Wk_hi;   s.lo[4] = Wk_lo;   s.prefix[4] = 7168;
        s.X[5] = Wv;    s.hi[5] = Wv_hi;   s.lo[5] = Wv_lo;   s.prefix[5] = 7680;
        split_all_kernel<<<8192, 256>>>(s);
    }

    // #3 transpose-splits of projection weights
    {
        TSplit2 t = {};
        t.X[0] = Wq_proj; t.X[1] = Wp_proj;
        t.hi[0] = WqpT_hi; t.hi[1] = WppT_hi;
        t.lo[0] = WqpT_lo; t.lo[1] = WppT_lo;
        tsplit_kernel<<<dim3(32, 32, 2), 256>>>(t);
    }

    // #4 bias combines
    {
        BiasBatch bb = {};
        bb.W[0] = Wq; bb.W[1] = Wk; bb.W[2] = Wv;
        bb.bin[0] = bq_proj; bb.bin[1] = bp_proj; bb.bin[2] = bp_proj;
        bb.badd[0] = bq; bb.badd[1] = bk; bb.badd[2] = bv;
        bb.out[0] = bqc; bb.out[1] = bkc; bb.out[2] = bvc;
        bias_combine_kernel<<<dim3(DIM / 8, 3), 256>>>(bb);
    }

    // #5 weight combines on tensor cores, emitting bf16 hi/lo directly
    {
        MmaB mb = {};
        mb.nj = 3;
        mb.j[0] = {Wq_hi, Wq_lo, WqpT_hi, WqpT_lo, nullptr, nullptr,
                   Wqc_hi, Wqc_lo, 0};
        mb.j[1] = {Wk_hi, Wk_lo, WppT_hi, WppT_lo, nullptr, nullptr,
                   Wkc_hi, Wkc_lo, 64};
        mb.j[2] = {Wv_hi, Wv_lo, WppT_hi, WppT_lo, nullptr, nullptr,
                   Wvc_hi, Wvc_lo, 128};
        mma_gemm<<<192, 256, MMA_SMEM>>>(mb);
    }

    // #6 merged big GEMMs: qh (512 blocks), Kb (256), Vb (256)  [ncu target]
    {
        MmaB mb = {};
        mb.nj = 3;
        mb.j[0] = {q_hi, q_lo, Wqc_hi, Wqc_lo, bqc, qh, nullptr, nullptr, 0};
        mb.j[1] = {bank_hi, bank_lo, Wkc_hi, Wkc_lo, bkc, Kb, nullptr, nullptr, 512};
        mb.j[2] = {bank_hi, bank_lo, Wvc_hi, Wvc_lo, bvc, Vb, nullptr, nullptr, 768};
        mma_gemm<<<1024, 256, MMA_SMEM>>>(mb);
    }

    // #7 attention (emits ctx splits)
    attention_kernel<<<BATCH, 128>>>(qh, Kb, Vb, topk, ctx_hi, ctx_lo, out_attn);

    // #8 out projection
    {
        MmaB mb = {};
        mb.nj = 1;
        mb.j[0] = {ctx_hi, ctx_lo, Wo_hi, Wo_lo, bo, out_ctx, nullptr, nullptr, 0};
        mma_gemm<<<512, 256, MMA_SMEM>>>(mb);
    }
}

// round 7
// speedup vs baseline: 4.2351x; 1.0392x over previous
#include <cuda_runtime.h>
#include <cuda_bf16.h>
#include <math.h>

#define BATCH 8192
#define PROTO 4096
#define DIM   1024
#define HEADS 16
#define DH    64
#define KSEL  6

typedef unsigned long long ull;
typedef unsigned int u32;

// ---------------- device scratch ----------------
__device__ float g_bqc[DIM];
__device__ float g_bkc[DIM];
__device__ float g_bvc[DIM];
__device__ float g_qh[BATCH * DIM];
__device__ float g_Kb[PROTO * DIM];
__device__ float g_Vb[PROTO * DIM];
__device__ int   g_topk[BATCH * KSEL];

__device__ __align__(16) __nv_bfloat16 g_q_hi[BATCH * DIM];
__device__ __align__(16) __nv_bfloat16 g_q_lo[BATCH * DIM];
__device__ __align__(16) __nv_bfloat16 g_bank_hi[PROTO * DIM];
__device__ __align__(16) __nv_bfloat16 g_bank_lo[PROTO * DIM];
__device__ __align__(16) __nv_bfloat16 g_ctx_hi[BATCH * DIM];
__device__ __align__(16) __nv_bfloat16 g_ctx_lo[BATCH * DIM];
__device__ __align__(16) __nv_bfloat16 g_Wq_hi[DIM * DIM];
__device__ __align__(16) __nv_bfloat16 g_Wq_lo[DIM * DIM];
__device__ __align__(16) __nv_bfloat16 g_Wk_hi[DIM * DIM];
__device__ __align__(16) __nv_bfloat16 g_Wk_lo[DIM * DIM];
__device__ __align__(16) __nv_bfloat16 g_Wv_hi[DIM * DIM];
__device__ __align__(16) __nv_bfloat16 g_Wv_lo[DIM * DIM];
__device__ __align__(16) __nv_bfloat16 g_WqpT_hi[DIM * DIM];
__device__ __align__(16) __nv_bfloat16 g_WqpT_lo[DIM * DIM];
__device__ __align__(16) __nv_bfloat16 g_WppT_hi[DIM * DIM];
__device__ __align__(16) __nv_bfloat16 g_WppT_lo[DIM * DIM];
__device__ __align__(16) __nv_bfloat16 g_Wqc_hi[DIM * DIM];
__device__ __align__(16) __nv_bfloat16 g_Wqc_lo[DIM * DIM];
__device__ __align__(16) __nv_bfloat16 g_Wkc_hi[DIM * DIM];
__device__ __align__(16) __nv_bfloat16 g_Wkc_lo[DIM * DIM];
__device__ __align__(16) __nv_bfloat16 g_Wvc_hi[DIM * DIM];
__device__ __align__(16) __nv_bfloat16 g_Wvc_lo[DIM * DIM];
__device__ __align__(16) __nv_bfloat16 g_Wo_hi[DIM * DIM];
__device__ __align__(16) __nv_bfloat16 g_Wo_lo[DIM * DIM];

// ---------------- low-level helpers ----------------
__device__ __forceinline__ u32 smem_u32(const void* p) {
    u32 a;
    asm("{ .reg .u64 t; cvta.to.shared.u64 t, %1; cvt.u32.u64 %0, t; }"
        : "=r"(a) : "l"(p));
    return a;
}
__device__ __forceinline__ void cp_async16(u32 dst, const void* src) {
    asm volatile("cp.async.cg.shared.global [%0], [%1], 16;"
                 :: "r"(dst), "l"(src) : "memory");
}
__device__ __forceinline__ void cp_commit() {
    asm volatile("cp.async.commit_group;" ::: "memory");
}
__device__ __forceinline__ void cp_wait2() {
    asm volatile("cp.async.wait_group 2;" ::: "memory");
}
__device__ __forceinline__ void cp_wait1() {
    asm volatile("cp.async.wait_group 1;" ::: "memory");
}
__device__ __forceinline__ void cp_wait0() {
    asm volatile("cp.async.wait_group 0;" ::: "memory");
}
__device__ __forceinline__ void ldsm4(u32* d, u32 addr) {
    asm volatile("ldmatrix.sync.aligned.m8n8.x4.shared.b16 {%0,%1,%2,%3}, [%4];"
                 : "=r"(d[0]), "=r"(d[1]), "=r"(d[2]), "=r"(d[3]) : "r"(addr));
}
__device__ __forceinline__ void mma_bf16(float* c, const u32* a, u32 b0, u32 b1) {
    asm volatile("mma.sync.aligned.m16n8k16.row.col.f32.bf16.bf16.f32 "
                 "{%0,%1,%2,%3},{%4,%5,%6,%7},{%8,%9},{%0,%1,%2,%3};"
                 : "+f"(c[0]), "+f"(c[1]), "+f"(c[2]), "+f"(c[3])
                 : "r"(a[0]), "r"(a[1]), "r"(a[2]), "r"(a[3]), "r"(b0), "r"(b1));
}
__device__ __forceinline__ u32 pack_bf16(float x, float y) {
    __nv_bfloat162 p = __floats2bfloat162_rn(x, y);
    return *(u32*)&p;
}

// ---------------- flattened split: fp32 -> bf16 hi/lo, 6 jobs -------------
struct SplitAll {
    const float* X[6];
    __nv_bfloat16* hi[6];
    __nv_bfloat16* lo[6];
    int prefix[6];
};
__global__ void split_all_kernel(SplitAll p) {
    const int bid = blockIdx.x;
    int z = 0;
    #pragma unroll
    for (int q = 1; q < 6; q++) if (bid >= p.prefix[q]) z = q;
    size_t id = (((size_t)(bid - p.prefix[z])) * 256 + threadIdx.x) * 8;
    const float4* src = (const float4*)(p.X[z] + id);
    float4 a = src[0], b = src[1];
    float xs[8] = {a.x, a.y, a.z, a.w, b.x, b.y, b.z, b.w};
    __nv_bfloat16 h[8], l[8];
    #pragma unroll
    for (int i = 0; i < 8; i++) {
        h[i] = __float2bfloat16(xs[i]);
        l[i] = __float2bfloat16(xs[i] - __bfloat162float(h[i]));
    }
    *(uint4*)(p.hi[z] + id) = *(uint4*)h;
    *(uint4*)(p.lo[z] + id) = *(uint4*)l;
}

// ---------------- transpose-split ----------------
struct TSplit2 {
    const float* X[2];
    __nv_bfloat16* hi[2];
    __nv_bfloat16* lo[2];
};
__global__ void tsplit_kernel(TSplit2 p) {
    __shared__ float t[32][33];
    const int z = blockIdx.z;
    const float* __restrict__ X = p.X[z];
    const int tx = threadIdx.x & 31, ty = threadIdx.x >> 5;
    const int bx = blockIdx.x * 32, by = blockIdx.y * 32;
    #pragma unroll
    for (int i = 0; i < 4; i++)
        t[ty + 8 * i][tx] = X[(size_t)(by + ty + 8 * i) * DIM + bx + tx];
    __syncthreads();
    #pragma unroll
    for (int i = 0; i < 4; i++) {
        float x = t[tx][ty + 8 * i];
        __nv_bfloat16 h = __float2bfloat16(x);
        __nv_bfloat16 l = __float2bfloat16(x - __bfloat162float(h));
        size_t o = (size_t)(bx + ty + 8 * i) * DIM + by + tx;
        p.hi[z][o] = h;
        p.lo[z][o] = l;
    }
}

// ---------------- mma.sync GEMM (bf16x3), 512 threads, 1 sync/stage -------
#define BK 32
#define SKB 40                        /* bf16 row stride in smem (80 B) */
#define TILE_SM (128 * SKB * 2)       /* 10240 B */
#define STAGE_SM (4 * TILE_SM)        /* 40960 B */
#define MMA_SMEM (4 * STAGE_SM)       /* 163840 B */

struct MmaJob {
    const __nv_bfloat16 *Ahi, *Alo, *Bhi, *Blo;
    const float* bias;
    float* C;
    __nv_bfloat16 *Chi, *Clo;
    int prefix;
};
struct MmaB {
    MmaJob j[3];
    int nj;
};

__global__ __launch_bounds__(512, 1)
void mma_gemm(MmaB p) {
    extern __shared__ __align__(16) char sm[];
    const u32 sbase = smem_u32(sm);

    const int bid = blockIdx.x;
    int z = 0;
    if (p.nj > 1 && bid >= p.j[1].prefix) z = 1;
    if (p.nj > 2 && bid >= p.j[2].prefix) z = 2;
    const MmaJob& J = p.j[z];
    const int rel = bid - J.prefix;
    const int m0 = (rel >> 3) * 128, n0 = (rel & 7) * 128;

    const int tid = threadIdx.x, lane = tid & 31, wid = tid >> 5;
    const int wm = wid >> 2, wn = wid & 3;   // 4x4 warps, 32x32 warp tile

    // loads: each thread handles row=tid>>2, seg=tid&3 across all 4 tiles
    const int lrow = tid >> 2, lseg = tid & 3;
    const __nv_bfloat16* gAhi = J.Ahi + (size_t)(m0 + lrow) * DIM + lseg * 8;
    const __nv_bfloat16* gAlo = J.Alo + (size_t)(m0 + lrow) * DIM + lseg * 8;
    const __nv_bfloat16* gBhi = J.Bhi + (size_t)(n0 + lrow) * DIM + lseg * 8;
    const __nv_bfloat16* gBlo = J.Blo + (size_t)(n0 + lrow) * DIM + lseg * 8;
    const u32 dbase = lrow * (SKB * 2) + lseg * 16;

    #define LOAD_STAGE(s)                                                 \
    do {                                                                  \
        const u32 st_ = sbase + ((s) & 3) * STAGE_SM;                     \
        const int k0_ = (s) * BK;                                         \
        cp_async16(st_ + dbase,               gAhi + k0_);                \
        cp_async16(st_ + TILE_SM + dbase,     gAlo + k0_);                \
        cp_async16(st_ + 2 * TILE_SM + dbase, gBhi + k0_);                \
        cp_async16(st_ + 3 * TILE_SM + dbase, gBlo + k0_);                \
        cp_commit();                                                      \
    } while (0)

    float c[2][4][4];
    #pragma unroll
    for (int i = 0; i < 2; i++)
        #pragma unroll
        for (int j = 0; j < 4; j++)
            #pragma unroll
            for (int q = 0; q < 4; q++) c[i][j][q] = 0.0f;

    const int NS = DIM / BK;   // 32
    LOAD_STAGE(0);
    LOAD_STAGE(1);
    LOAD_STAGE(2);

    const u32 rowoff = (lane & 15) * (SKB * 2) + (lane >> 4) * 16;

    for (int s = 0; s < NS; s++) {
        // stage s complete when ≤ (number of still-pending later stages) remain
        if (s + 2 < NS) cp_wait2();
        else if (s + 1 < NS) cp_wait1();
        else cp_wait0();
        __syncthreads();          // all loads of s visible; all consumed s-1
        if (s + 3 < NS) LOAD_STAGE(s + 3);   // overwrites buffer (s-1)&3

        const u32 st = sbase + (s & 3) * STAGE_SM;
        const u32 aHiB = st + (wm * 32) * (SKB * 2);
        const u32 aLoB = st + TILE_SM + (wm * 32) * (SKB * 2);
        const u32 bHiB = st + 2 * TILE_SM + (wn * 32) * (SKB * 2);
        const u32 bLoB = st + 3 * TILE_SM + (wn * 32) * (SKB * 2);

        #pragma unroll
        for (int kk = 0; kk < 2; kk++) {
            const u32 ko = kk * 32;   // 16 bf16 = 32 B
            u32 ah[2][4], al[2][4];
            ldsm4(ah[0], aHiB + rowoff + ko);
            ldsm4(ah[1], aHiB + 16 * (SKB * 2) + rowoff + ko);
            ldsm4(al[0], aLoB + rowoff + ko);
            ldsm4(al[1], aLoB + 16 * (SKB * 2) + rowoff + ko);
            u32 bh[2][4], bl[2][4];
            #pragma unroll
            for (int g = 0; g < 2; g++) {
                ldsm4(bh[g], bHiB + g * 16 * (SKB * 2) + rowoff + ko);
                ldsm4(bl[g], bLoB + g * 16 * (SKB * 2) + rowoff + ko);
            }
            #pragma unroll
            for (int mi = 0; mi < 2; mi++)
                #pragma unroll
                for (int g = 0; g < 2; g++)
                    #pragma unroll
                    for (int sub = 0; sub < 2; sub++) {
                        float* cc = c[mi][g * 2 + sub];
                        mma_bf16(cc, ah[mi], bh[g][sub], bh[g][sub + 2]);
                        mma_bf16(cc, ah[mi], bl[g][sub], bl[g][sub + 2]);
                        mma_bf16(cc, al[mi], bh[g][sub], bh[g][sub + 2]);
                    }
        }
    }

    // epilogue
    if (J.C) {
        float* __restrict__ C = J.C;
        const float* __restrict__ bias = J.bias;
        #pragma unroll
        for (int mi = 0; mi < 2; mi++) {
            const int row = m0 + wm * 32 + mi * 16 + (lane >> 2);
            #pragma unroll
            for (int ni = 0; ni < 4; ni++) {
                const int col = n0 + wn * 32 + ni * 8 + 2 * (lane & 3);
                float2 bv = bias ? *(const float2*)(bias + col)
                                 : make_float2(0.0f, 0.0f);
                const float* cc = c[mi][ni];
                *(float2*)&C[(size_t)row * DIM + col] =
                    make_float2(cc[0] + bv.x, cc[1] + bv.y);
                *(float2*)&C[(size_t)(row + 8) * DIM + col] =
                    make_float2(cc[2] + bv.x, cc[3] + bv.y);
            }
        }
    } else {
        __nv_bfloat16* __restrict__ Chi = J.Chi;
        __nv_bfloat16* __restrict__ Clo = J.Clo;
        #pragma unroll
        for (int mi = 0; mi < 2; mi++) {
            const int row = m0 + wm * 32 + mi * 16 + (lane >> 2);
            #pragma unroll
            for (int ni = 0; ni < 4; ni++) {
                const int col = n0 + wn * 32 + ni * 8 + 2 * (lane & 3);
                const float* cc = c[mi][ni];
                #pragma unroll
                for (int rr = 0; rr < 2; rr++) {
                    float x0 = cc[rr * 2], x1 = cc[rr * 2 + 1];
                    __nv_bfloat16 h0 = __float2bfloat16(x0);
                    __nv_bfloat16 h1 = __float2bfloat16(x1);
                    float l0 = x0 - __bfloat162float(h0);
                    float l1 = x1 - __bfloat162float(h1);
                    size_t o = (size_t)(row + rr * 8) * DIM + col;
                    __nv_bfloat162 hp; hp.x = h0; hp.y = h1;
                    *(u32*)&Chi[o] = *(u32*)&hp;
                    *(u32*)&Clo[o] = pack_bf16(l0, l1);
                }
            }
        }
    }
    #undef LOAD_STAGE
}

// ---------------- batched bias combine ----------------
struct BiasBatch {
    const float* W[3];
    const float* bin[3];
    const float* badd[3];
    float*       out[3];
};

__global__ void bias_combine_kernel(BiasBatch p) {
    const int z = blockIdx.y;
    const int warp = threadIdx.x >> 5, lane = threadIdx.x & 31;
    const int i = blockIdx.x * 8 + warp;
    const float* __restrict__ row = p.W[z] + (size_t)i * DIM;
    const float* __restrict__ bin = p.bin[z];
    float s = 0.0f;
    for (int t = lane; t < DIM; t += 32) s = fmaf(row[t], bin[t], s);
    #pragma unroll
    for (int o = 16; o; o >>= 1) s += __shfl_down_sync(0xffffffffu, s, o);
    if (lane == 0) p.out[z][i] = s + p.badd[z][i];
}

// ---------------- top-6 per row ----------------
__global__ void topk6_kernel(const float* __restrict__ logits,
                             int* __restrict__ topk) {
    const int b = blockIdx.x;
    const int tid = threadIdx.x;   // 256
    const int lane = tid & 31, wid = tid >> 5;
    const float* __restrict__ src = logits + (size_t)b * PROTO;

    float v[KSEL]; int ix[KSEL];
    #pragma unroll
    for (int q = 0; q < KSEL; q++) { v[q] = -INFINITY; ix[q] = 0x7fffffff; }

    #pragma unroll
    for (int pp = 0; pp < PROTO / 256 / 4; pp++) {
        int i = (tid + pp * 256) * 4;
        float4 x4 = *(const float4*)(src + i);
        float xs[4] = {x4.x, x4.y, x4.z, x4.w};
        #pragma unroll
        for (int u = 0; u < 4; u++) {
            float x = xs[u];
            if (x > v[KSEL - 1]) {
                v[KSEL - 1] = x; ix[KSEL - 1] = i + u;
                #pragma unroll
                for (int q = KSEL - 1; q > 0; q--) {
                    if (v[q] > v[q - 1]) {
                        float tv = v[q]; v[q] = v[q - 1]; v[q - 1] = tv;
                        int ti = ix[q]; ix[q] = ix[q - 1]; ix[q - 1] = ti;
                    }
                }
            }
        }
    }

    __shared__ float wv[8][KSEL];
    __shared__ int   wi[8][KSEL];
    #pragma unroll
    for (int t = 0; t < KSEL; t++) {
        float cv = v[0]; int ci = ix[0];
        #pragma unroll
        for (int o = 16; o; o >>= 1) {
            float ov = __shfl_down_sync(0xffffffffu, cv, o);
            int oi = __shfl_down_sync(0xffffffffu, ci, o);
            if (ov > cv || (ov == cv && oi < ci)) { cv = ov; ci = oi; }
        }
        cv = __shfl_sync(0xffffffffu, cv, 0);
        ci = __shfl_sync(0xffffffffu, ci, 0);
        if (lane == 0) { wv[wid][t] = cv; wi[wid][t] = ci; }
        if (ix[0] == ci) {
            #pragma unroll
            for (int q = 0; q < KSEL - 1; q++) { v[q] = v[q + 1]; ix[q] = ix[q + 1]; }
            v[KSEL - 1] = -INFINITY; ix[KSEL - 1] = 0x7fffffff;
        }
    }
    __syncthreads();

    if (wid == 0) {
        float lv[KSEL]; int li[KSEL];
        #pragma unroll
        for (int q = 0; q < KSEL; q++) {
            lv[q] = (lane < 8) ? wv[lane][q] : -INFINITY;
            li[q] = (lane < 8) ? wi[lane][q] : 0x7fffffff;
        }
        #pragma unroll
        for (int t = 0; t < KSEL; t++) {
            float cv = lv[0]; int ci = li[0];
            #pragma unroll
            for (int o = 16; o; o >>= 1) {
                float ov = __shfl_down_sync(0xffffffffu, cv, o);
                int oi = __shfl_down_sync(0xffffffffu, ci, o);
                if (ov > cv || (ov == cv && oi < ci)) { cv = ov; ci = oi; }
            }
            cv = __shfl_sync(0xffffffffu, cv, 0);
            ci = __shfl_sync(0xffffffffu, ci, 0);
            if (lane == 0) topk[(size_t)b * KSEL + t] = ci;
            if (li[0] == ci) {
                #pragma unroll
                for (int q = 0; q < KSEL - 1; q++) { lv[q] = lv[q + 1]; li[q] = li[q + 1]; }
                lv[KSEL - 1] = -INFINITY; li[KSEL - 1] = 0x7fffffff;
            }
        }
    }
}

// ---------------- per-row attention (emits ctx hi/lo splits) --------------
__global__ void attention_kernel(const float* __restrict__ qh,
                                 const float* __restrict__ Kb,
                                 const float* __restrict__ Vb,
                                 const int* __restrict__ topk,
                                 __nv_bfloat16* __restrict__ ctx_hi,
                                 __nv_bfloat16* __restrict__ ctx_lo,
                                 float* __restrict__ attn_out) {
    const int b = blockIdx.x;
    const int tid = threadIdx.x;   // 128
    __shared__ float q_s[DIM];
    __shared__ float k_s[KSEL][DIM];
    __shared__ int   idx_s[KSEL];
    __shared__ float s_s[HEADS][KSEL];

    if (tid < KSEL) idx_s[tid] = topk[(size_t)b * KSEL + tid];
    __syncthreads();

    {
        const float4* q4 = (const float4*)(qh + (size_t)b * DIM);
        float4* qs4 = (float4*)q_s;
        for (int i = tid; i < DIM / 4; i += 128) qs4[i] = q4[i];
        for (int i = tid; i < KSEL * (DIM / 4); i += 128) {
            int j = i / (DIM / 4), c = i % (DIM / 4);
            ((float4*)k_s[j])[c] =
                ((const float4*)(Kb + (size_t)idx_s[j] * DIM))[c];
        }
    }
    __syncthreads();

    for (int p = tid; p < HEADS * KSEL; p += 128) {
        int h = p / KSEL, j = p % KSEL;
        float dot = 0.0f;
        #pragma unroll
        for (int d = 0; d < DH; d++)
            dot = fmaf(q_s[h * DH + d], k_s[j][h * DH + d], dot);
        s_s[h][j] = dot * 0.125f;
    }
    __syncthreads();

    if (tid < HEADS) {
        int h = tid;
        float m = s_s[h][0];
        #pragma unroll
        for (int j = 1; j < KSEL; j++) m = fmaxf(m, s_s[h][j]);
        float e[KSEL], sum = 0.0f;
        #pragma unroll
        for (int j = 0; j < KSEL; j++) { e[j] = expf(s_s[h][j] - m); sum += e[j]; }
        float inv = 1.0f / sum;
        #pragma unroll
        for (int j = 0; j < KSEL; j++) s_s[h][j] = e[j] * inv;
    }
    __syncthreads();

    if (tid < KSEL) {
        float m = 0.0f;
        #pragma unroll
        for (int h = 0; h < HEADS; h++) m += s_s[h][tid];
        attn_out[(size_t)b * KSEL + tid] = m * (1.0f / HEADS);
    }

    for (int d = tid; d < DIM; d += 128) {
        int h = d / DH;
        float acc = 0.0f;
        #pragma unroll
        for (int j = 0; j < KSEL; j++)
            acc = fmaf(s_s[h][j], Vb[(size_t)idx_s[j] * DIM + d], acc);
        __nv_bfloat16 hh = __float2bfloat16(acc);
        ctx_hi[(size_t)b * DIM + d] = hh;
        ctx_lo[(size_t)b * DIM + d] =
            __float2bfloat16(acc - __bfloat162float(hh));
    }
}

// ---------------- host launcher -------------------------------------------
extern "C" void kernel_launch(void* const* d_in, const int* in_sizes, int n_in,
                              void* d_out, int out_size) {
    const float* query  = (const float*)d_in[0];
    const float* bank   = (const float*)d_in[1];
    const float* logits = (const float*)d_in[2];
    const float* Wq_proj = (const float*)d_in[3];
    const float* bq_proj = (const float*)d_in[4];
    const float* Wp_proj = (const float*)d_in[5];
    const float* bp_proj = (const float*)d_in[6];
    const float* Wq = (const float*)d_in[7];
    const float* bq = (const float*)d_in[8];
    const float* Wk = (const float*)d_in[9];
    const float* bk = (const float*)d_in[10];
    const float* Wv = (const float*)d_in[11];
    const float* bv = (const float*)d_in[12];
    const float* Wo = (const float*)d_in[13];
    const float* bo = (const float*)d_in[14];

    float* out = (float*)d_out;
    float* out_ctx  = out;
    float* out_attn = out + (size_t)BATCH * DIM;

    float *bqc, *bkc, *bvc, *qh, *Kb, *Vb;
    int* topk;
    cudaGetSymbolAddress((void**)&bqc, g_bqc);
    cudaGetSymbolAddress((void**)&bkc, g_bkc);
    cudaGetSymbolAddress((void**)&bvc, g_bvc);
    cudaGetSymbolAddress((void**)&qh,  g_qh);
    cudaGetSymbolAddress((void**)&Kb,  g_Kb);
    cudaGetSymbolAddress((void**)&Vb,  g_Vb);
    cudaGetSymbolAddress((void**)&topk, g_topk);

    __nv_bfloat16 *q_hi, *q_lo, *bank_hi, *bank_lo, *ctx_hi, *ctx_lo;
    __nv_bfloat16 *Wq_hi, *Wq_lo, *Wk_hi, *Wk_lo, *Wv_hi, *Wv_lo;
    __nv_bfloat16 *WqpT_hi, *WqpT_lo, *WppT_hi, *WppT_lo;
    __nv_bfloat16 *Wqc_hi, *Wqc_lo, *Wkc_hi, *Wkc_lo, *Wvc_hi, *Wvc_lo, *Wo_hi, *Wo_lo;
    cudaGetSymbolAddress((void**)&q_hi, g_q_hi);
    cudaGetSymbolAddress((void**)&q_lo, g_q_lo);
    cudaGetSymbolAddress((void**)&bank_hi, g_bank_hi);
    cudaGetSymbolAddress((void**)&bank_lo, g_bank_lo);
    cudaGetSymbolAddress((void**)&ctx_hi, g_ctx_hi);
    cudaGetSymbolAddress((void**)&ctx_lo, g_ctx_lo);
    cudaGetSymbolAddress((void**)&Wq_hi, g_Wq_hi);
    cudaGetSymbolAddress((void**)&Wq_lo, g_Wq_lo);
    cudaGetSymbolAddress((void**)&Wk_hi, g_Wk_hi);
    cudaGetSymbolAddress((void**)&Wk_lo, g_Wk_lo);
    cudaGetSymbolAddress((void**)&Wv_hi, g_Wv_hi);
    cudaGetSymbolAddress((void**)&Wv_lo, g_Wv_lo);
    cudaGetSymbolAddress((void**)&WqpT_hi, g_WqpT_hi);
    cudaGetSymbolAddress((void**)&WqpT_lo, g_WqpT_lo);
    cudaGetSymbolAddress((void**)&WppT_hi, g_WppT_hi);
    cudaGetSymbolAddress((void**)&WppT_lo, g_WppT_lo);
    cudaGetSymbolAddress((void**)&Wqc_hi, g_Wqc_hi);
    cudaGetSymbolAddress((void**)&Wqc_lo, g_Wqc_lo);
    cudaGetSymbolAddress((void**)&Wkc_hi, g_Wkc_hi);
    cudaGetSymbolAddress((void**)&Wkc_lo, g_Wkc_lo);
    cudaGetSymbolAddress((void**)&Wvc_hi, g_Wvc_hi);
    cudaGetSymbolAddress((void**)&Wvc_lo, g_Wvc_lo);
    cudaGetSymbolAddress((void**)&Wo_hi, g_Wo_hi);
    cudaGetSymbolAddress((void**)&Wo_lo, g_Wo_lo);

    cudaFuncSetAttribute(mma_gemm,
                         cudaFuncAttributeMaxDynamicSharedMemorySize, MMA_SMEM);

    // #1 topk (independent)
    topk6_kernel<<<BATCH, 256>>>(logits, topk);

    // #2 all row-splits in one launch
    {
        SplitAll s = {};
        s.X[0] = query; s.hi[0] = q_hi;    s.lo[0] = q_lo;    s.prefix[0] = 0;
        s.X[1] = bank;  s.hi[1] = bank_hi; s.lo[1] = bank_lo; s.prefix[1] = 4096;
        s.X[2] = Wo;    s.hi[2] = Wo_hi;   s.lo[2] = Wo_lo;   s.prefix[2] = 6144;
        s.X[3] = Wq;    s.hi[3] = Wq_hi;   s.lo[3] = Wq_lo;   s.prefix[3] = 6656;
        s.X[4] = Wk;    s.hi[4] = Wk_hi;   s.lo[4] = Wk_lo;   s.prefix[4] = 7168;
        s.X[5] = Wv;    s.hi[5] = Wv_hi;   s.lo[5] = Wv_lo;   s.prefix[5] = 7680;
        split_all_kernel<<<8192, 256>>>(s);
    }

    // #3 transpose-splits of projection weights
    {
        TSplit2 t = {};
        t.X[0] = Wq_proj; t.X[1] = Wp_proj;
        t.hi[0] = WqpT_hi; t.hi[1] = WppT_hi;
        t.lo[0] = WqpT_lo; t.lo[1] = WppT_lo;
        tsplit_kernel<<<dim3(32, 32, 2), 256>>>(t);
    }

    // #4 bias combines
    {
        BiasBatch bb = {};
        bb.W[0] = Wq; bb.W[1] = Wk; bb.W[2] = Wv;
        bb.bin[0] = bq_proj; bb.bin[1] = bp_proj; bb.bin[2] = bp_proj;
        bb.badd[0] = bq; bb.badd[1] = bk; bb.badd[2] = bv;
        bb.out[0] = bqc; bb.out[1] = bkc; bb.out[2] = bvc;
        bias_combine_kernel<<<dim3(DIM / 8, 3), 256>>>(bb);
    }

    // #5 weight combines on tensor cores, bf16 hi/lo direct output
    {
        MmaB mb = {};
        mb.nj = 3;
        mb.j[0] = {Wq_hi, Wq_lo, WqpT_hi, WqpT_lo, nullptr, nullptr,
                   Wqc_hi, Wqc_lo, 0};
        mb.j[1] = {Wk_hi, Wk_lo, WppT_hi, WppT_lo, nullptr, nullptr,
                   Wkc_hi, Wkc_lo, 64};
        mb.j[2] = {Wv_hi, Wv_lo, WppT_hi, WppT_lo, nullptr, nullptr,
                   Wvc_hi, Wvc_lo, 128};
        mma_gemm<<<192, 512, MMA_SMEM>>>(mb);
    }

    // #6 merged big GEMMs: qh (512 blocks), Kb (256), Vb (256)
    {
        MmaB mb = {};
        mb.nj = 3;
        mb.j[0] = {q_hi, q_lo, Wqc_hi, Wqc_lo, bqc, qh, nullptr, nullptr, 0};
        mb.j[1] = {bank_hi, bank_lo, Wkc_hi, Wkc_lo, bkc, Kb, nullptr, nullptr, 512};
        mb.j[2] = {bank_hi, bank_lo, Wvc_hi, Wvc_lo, bvc, Vb, nullptr, nullptr, 768};
        mma_gemm<<<1024, 512, MMA_SMEM>>>(mb);
    }

    // #7 attention
    attention_kernel<<<BATCH, 128>>>(qh, Kb, Vb, topk, ctx_hi, ctx_lo, out_attn);

    // #8 out projection
    {
        MmaB mb = {};
        mb.nj = 1;
        mb.j[0] = {ctx_hi, ctx_lo, Wo_hi, Wo_lo, bo, out_ctx, nullptr, nullptr, 0};
        mma_gemm<<<512, 512, MMA_SMEM>>>(mb);
    }
}